// round 1
// baseline (speedup 1.0000x reference)
#include <cuda_runtime.h>

// Problem constants
#define B_ 8
#define S_ 1024
#define D_ 1024
#define H_ 16
#define P_ 64
#define M_TOT (B_ * S_)   // 8192

// Scratch (allocation-free rule: __device__ globals)
__device__ float g_Q[B_ * S_ * D_];
__device__ float g_K[B_ * S_ * D_];
__device__ float g_V[B_ * S_ * D_];
__device__ float g_A[B_ * S_ * D_];

// ---------------------------------------------------------------------------
// SGEMM (NT): C[m,n] = sum_k A[m,k] * W[n,k] + bias[n]   (+ optional sigmoid)
// A: M x K row-major, W: N x K row-major. BM=BN=128, BK=8, 256 threads, 8x8/thr
// ---------------------------------------------------------------------------
template <int SIG>
__global__ void __launch_bounds__(256) sgemm_nt_bias(
    const float* __restrict__ A, const float* __restrict__ W,
    const float* __restrict__ bias, float* __restrict__ C,
    int M, int N, int K)
{
    __shared__ float As[8][128];
    __shared__ float Ws[8][128];

    const int tid  = threadIdx.x;
    const int bm   = blockIdx.y * 128;
    const int bn   = blockIdx.x * 128;
    const int lr   = tid >> 1;            // 0..127 row within tile
    const int lc   = (tid & 1) * 4;       // 0 or 4  (k offset)
    const int rowb = (tid >> 4) * 8;      // compute rows
    const int colb = (tid & 15) * 8;      // compute cols

    const float* Ag = A + (size_t)(bm + lr) * K + lc;
    const float* Wg = W + (size_t)(bn + lr) * K + lc;

    float acc[8][8];
#pragma unroll
    for (int i = 0; i < 8; i++)
#pragma unroll
        for (int j = 0; j < 8; j++) acc[i][j] = 0.f;

    for (int k0 = 0; k0 < K; k0 += 8) {
        float4 a4 = *(const float4*)(Ag + k0);
        float4 w4 = *(const float4*)(Wg + k0);
        As[lc + 0][lr] = a4.x; As[lc + 1][lr] = a4.y;
        As[lc + 2][lr] = a4.z; As[lc + 3][lr] = a4.w;
        Ws[lc + 0][lr] = w4.x; Ws[lc + 1][lr] = w4.y;
        Ws[lc + 2][lr] = w4.z; Ws[lc + 3][lr] = w4.w;
        __syncthreads();

#pragma unroll
        for (int kk = 0; kk < 8; kk++) {
            float ra[8], rb[8];
            *(float4*)&ra[0] = *(const float4*)&As[kk][rowb];
            *(float4*)&ra[4] = *(const float4*)&As[kk][rowb + 4];
            *(float4*)&rb[0] = *(const float4*)&Ws[kk][colb];
            *(float4*)&rb[4] = *(const float4*)&Ws[kk][colb + 4];
#pragma unroll
            for (int i = 0; i < 8; i++)
#pragma unroll
                for (int j = 0; j < 8; j++)
                    acc[i][j] += ra[i] * rb[j];
        }
        __syncthreads();
    }

    float bb[8];
    *(float4*)&bb[0] = *(const float4*)&bias[bn + colb];
    *(float4*)&bb[4] = *(const float4*)&bias[bn + colb + 4];

#pragma unroll
    for (int i = 0; i < 8; i++) {
        float out[8];
#pragma unroll
        for (int j = 0; j < 8; j++) {
            float v = acc[i][j] + bb[j];
            if (SIG) v = 1.f / (1.f + __expf(-v));
            out[j] = v;
        }
        float* Cp = C + (size_t)(bm + rowb + i) * N + bn + colb;
        *(float4*)&Cp[0] = *(const float4*)&out[0];
        *(float4*)&Cp[4] = *(const float4*)&out[4];
    }
}

// ---------------------------------------------------------------------------
// Fused "attention" middle stage. One block per s (1024 blocks, 256 threads).
//
// For fixed s:
//   score[b,p,q] = (1/8) * sum_h Q[b,s,h*64+p] * K[b,s,h*64+q]
//   attn[b,p,q]  = exp(score[b,p,q]) / sum_b' exp(score[b',p,q])   (batch softmax)
//   g_A[b,s,h*64+p] = sum_q attn[b,p,q] * V[b,s,h*64+q]
//
// smem: ES[8][64][68] (exp-scores, stride-68 pad for conflict-free float4),
//       R[16384] holds Q|K in pass1, then V (stride-68 padded) in pass2.
// ---------------------------------------------------------------------------
#define ES_STRIDE 68
#define ES_PER_B  (64 * ES_STRIDE)        // 4352
#define VS_PER_B  (16 * ES_STRIDE)        // 1088
#define SMEM_FLOATS (8 * ES_PER_B + 16384)  // 51200 floats = 200 KB

__global__ void __launch_bounds__(256) attn_kernel()
{
    extern __shared__ float sm[];
    float* ES = sm;
    float* R  = sm + 8 * ES_PER_B;

    const int s = blockIdx.x;
    const int t = threadIdx.x;

    // Load Q,K rows for all 8 batches at this s (coalesced float4)
    for (int f = t; f < 8 * 256; f += 256) {
        const int b  = f >> 8;
        const int d4 = f & 255;
        const size_t g = ((size_t)b * S_ + s) * 256 + d4;
        ((float4*)R)[f]          = ((const float4*)g_Q)[g];
        ((float4*)(R + 8192))[f] = ((const float4*)g_K)[g];
    }
    __syncthreads();

    const float* Qs = R;
    const float* Ks = R + 8192;
    const int tp = (t >> 4) * 4;   // 4x4 micro-tile of the 64x64 score matrix
    const int tq = (t & 15) * 4;

    float sacc[4][4];
#pragma unroll
    for (int i = 0; i < 4; i++)
#pragma unroll
        for (int j = 0; j < 4; j++) sacc[i][j] = 0.f;

    // Pass 1: exp-scores for all b, accumulate batch-denominator in registers
    for (int b = 0; b < 8; b++) {
        const float* Qb = Qs + b * 1024;
        const float* Kb = Ks + b * 1024;
        float acc[4][4];
#pragma unroll
        for (int i = 0; i < 4; i++)
#pragma unroll
            for (int j = 0; j < 4; j++) acc[i][j] = 0.f;

#pragma unroll
        for (int h = 0; h < 16; h++) {
            float4 q4 = *(const float4*)(Qb + h * 64 + tp);
            float4 k4 = *(const float4*)(Kb + h * 64 + tq);
            float qa[4] = {q4.x, q4.y, q4.z, q4.w};
            float ka[4] = {k4.x, k4.y, k4.z, k4.w};
#pragma unroll
            for (int i = 0; i < 4; i++)
#pragma unroll
                for (int j = 0; j < 4; j++)
                    acc[i][j] += qa[i] * ka[j];
        }
        float* ESb = ES + b * ES_PER_B;
#pragma unroll
        for (int i = 0; i < 4; i++) {
            float4 e;
            e.x = __expf(acc[i][0] * 0.125f);
            e.y = __expf(acc[i][1] * 0.125f);
            e.z = __expf(acc[i][2] * 0.125f);
            e.w = __expf(acc[i][3] * 0.125f);
            sacc[i][0] += e.x; sacc[i][1] += e.y;
            sacc[i][2] += e.z; sacc[i][3] += e.w;
            *(float4*)&ESb[(tp + i) * ES_STRIDE + tq] = e;
        }
    }

    // Normalize in place (this thread owns the same (p,q) cells for all b)
    float rd[4][4];
#pragma unroll
    for (int i = 0; i < 4; i++)
#pragma unroll
        for (int j = 0; j < 4; j++) rd[i][j] = 1.f / sacc[i][j];

    for (int b = 0; b < 8; b++) {
        float* ESb = ES + b * ES_PER_B;
#pragma unroll
        for (int i = 0; i < 4; i++) {
            float4 e = *(const float4*)&ESb[(tp + i) * ES_STRIDE + tq];
            e.x *= rd[i][0]; e.y *= rd[i][1];
            e.z *= rd[i][2]; e.w *= rd[i][3];
            *(float4*)&ESb[(tp + i) * ES_STRIDE + tq] = e;
        }
    }
    __syncthreads();   // everyone done reading Q/K from R

    // Load V (stride-68 padded layout: Vs[b][h][q])
    for (int f = t; f < 8 * 256; f += 256) {
        const int b  = f >> 8;
        const int d4 = f & 255;
        const size_t g = ((size_t)b * S_ + s) * 256 + d4;
        float4 v = ((const float4*)g_V)[g];
        const int d = d4 * 4;
        const int h = d >> 6;
        const int q = d & 63;
        float* Vb = R + b * VS_PER_B + h * ES_STRIDE + q;
        Vb[0] = v.x; Vb[1] = v.y; Vb[2] = v.z; Vb[3] = v.w;
    }
    __syncthreads();

    // Pass 2: out[b,p,h] = sum_q attn[b,p,q] * V[b,h,q] -> g_A[b,s,h*64+p]
    for (int b = 0; b < 8; b++) {
        const float* ESb = ES + b * ES_PER_B;
        const float* Vb  = R + b * VS_PER_B;
        for (int o = t; o < 1024; o += 256) {
            const int h = o >> 6;
            const int p = o & 63;
            const float* er = ESb + p * ES_STRIDE;
            const float* vr = Vb + h * ES_STRIDE;
            float a = 0.f;
#pragma unroll
            for (int q = 0; q < 64; q += 4) {
                float4 e4 = *(const float4*)(er + q);
                float4 v4 = *(const float4*)(vr + q);
                a += e4.x * v4.x + e4.y * v4.y + e4.z * v4.z + e4.w * v4.w;
            }
            g_A[((size_t)b * S_ + s) * D_ + h * 64 + p] = a;
        }
    }
}

// ---------------------------------------------------------------------------
extern "C" void kernel_launch(void* const* d_in, const int* in_sizes, int n_in,
                              void* d_out, int out_size)
{
    const float* query = (const float*)d_in[0];
    const float* key   = (const float*)d_in[1];
    const float* value = (const float*)d_in[2];
    const float* Wq    = (const float*)d_in[3];
    const float* bq    = (const float*)d_in[4];
    const float* Wk    = (const float*)d_in[5];
    const float* bk    = (const float*)d_in[6];
    const float* Wv    = (const float*)d_in[7];
    const float* bv    = (const float*)d_in[8];
    const float* Wo    = (const float*)d_in[9];
    const float* bo    = (const float*)d_in[10];
    float* out = (float*)d_out;

    float *gQ, *gK, *gV, *gA;
    cudaGetSymbolAddress((void**)&gQ, g_Q);
    cudaGetSymbolAddress((void**)&gK, g_K);
    cudaGetSymbolAddress((void**)&gV, g_V);
    cudaGetSymbolAddress((void**)&gA, g_A);

    dim3 grid(D_ / 128, M_TOT / 128);   // (8, 64)
    sgemm_nt_bias<0><<<grid, 256>>>(query, Wq, bq, gQ, M_TOT, D_, D_);
    sgemm_nt_bias<0><<<grid, 256>>>(key,   Wk, bk, gK, M_TOT, D_, D_);
    sgemm_nt_bias<0><<<grid, 256>>>(value, Wv, bv, gV, M_TOT, D_, D_);

    const size_t smem = SMEM_FLOATS * sizeof(float);   // 200 KB
    cudaFuncSetAttribute(attn_kernel,
                         cudaFuncAttributeMaxDynamicSharedMemorySize, (int)smem);
    attn_kernel<<<S_, 256, smem>>>();

    sgemm_nt_bias<1><<<grid, 256>>>(gA, Wo, bo, out, M_TOT, D_, D_);
}

// round 4
// speedup vs baseline: 2.2029x; 2.2029x over previous
#include <cuda_runtime.h>
#include <cuda_bf16.h>
#include <cstdint>

// Problem constants
#define B_ 8
#define S_ 1024
#define D_ 1024
#define M_TOT (B_ * S_)   // 8192

// Scratch (allocation-free rule: __device__ globals)
__device__ float g_Q[B_ * S_ * D_];
__device__ float g_K[B_ * S_ * D_];
__device__ float g_V[B_ * S_ * D_];
__device__ float g_A[B_ * S_ * D_];

// ---------------------------------------------------------------------------
// Warp-level tensor-core helpers (base-target PTX: ldmatrix + mma.sync HMMA)
// ---------------------------------------------------------------------------
__device__ __forceinline__ uint32_t smem_u32(const void* p) {
    uint32_t a;
    asm("{ .reg .u64 t; cvta.to.shared.u64 t, %1; cvt.u32.u64 %0, t; }"
        : "=r"(a) : "l"(p));
    return a;
}

#define LDSM4(r, addr)                                                        \
    asm volatile("ldmatrix.sync.aligned.m8n8.x4.shared.b16 "                  \
                 "{%0, %1, %2, %3}, [%4];"                                    \
                 : "=r"((r)[0]), "=r"((r)[1]), "=r"((r)[2]), "=r"((r)[3])     \
                 : "r"(addr))

#define MMA16816(d, a, b)                                                     \
    asm volatile("mma.sync.aligned.m16n8k16.row.col.f32.bf16.bf16.f32 "       \
                 "{%0, %1, %2, %3}, {%4, %5, %6, %7}, {%8, %9}, "             \
                 "{%0, %1, %2, %3};"                                          \
                 : "+f"((d)[0]), "+f"((d)[1]), "+f"((d)[2]), "+f"((d)[3])     \
                 : "r"((a)[0]), "r"((a)[1]), "r"((a)[2]), "r"((a)[3]),        \
                   "r"((b)[0]), "r"((b)[1]))

// Split a float4 into bf16-hi + bf16-lo and store both (8B STS each)
__device__ __forceinline__ void cvt_split_sts(float4 v, uint32_t hi_addr,
                                              uint32_t lo_addr) {
    uint32_t h01, h23;
    asm("cvt.rn.bf16x2.f32 %0, %1, %2;" : "=r"(h01) : "f"(v.y), "f"(v.x));
    asm("cvt.rn.bf16x2.f32 %0, %1, %2;" : "=r"(h23) : "f"(v.w), "f"(v.z));
    float hx = __uint_as_float(h01 << 16);
    float hy = __uint_as_float(h01 & 0xffff0000u);
    float hz = __uint_as_float(h23 << 16);
    float hw = __uint_as_float(h23 & 0xffff0000u);
    uint32_t l01, l23;
    asm("cvt.rn.bf16x2.f32 %0, %1, %2;" : "=r"(l01) : "f"(v.y - hy), "f"(v.x - hx));
    asm("cvt.rn.bf16x2.f32 %0, %1, %2;" : "=r"(l23) : "f"(v.w - hw), "f"(v.z - hz));
    asm volatile("st.shared.v2.b32 [%0], {%1, %2};"
                 :: "r"(hi_addr), "r"(h01), "r"(h23) : "memory");
    asm volatile("st.shared.v2.b32 [%0], {%1, %2};"
                 :: "r"(lo_addr), "r"(l01), "r"(l23) : "memory");
}

// ---------------------------------------------------------------------------
// Split-bf16 HMMA GEMM (NT): C[m,n] = sum_k A[m,k]*W[n,k] + bias[n] (+sigmoid)
// BM=BN=128, BK=32, 256 threads (8 warps, 4m x 2n), warp tile 32x64.
// smem: 4 bf16 tiles (Ah/Al/Wh/Wl), 128 rows x 32 cols, row stride 80 bytes
// (conflict-free for ldmatrix 8-row phases: banks 20*r mod 32 tile perfectly).
// 3 MMA passes per k-step: Ah*Wh + Al*Wh + Ah*Wl  (lo*lo dropped, ~2^-16).
// ---------------------------------------------------------------------------
#define ROWB 80                       // bytes per smem row (32 bf16 + pad)
#define TILE_B (128 * ROWB)           // 10240 bytes per tile

template <int SIG>
__global__ void __launch_bounds__(256) gemm_tc(
    const float* __restrict__ A, const float* __restrict__ W,
    const float* __restrict__ bias, float* __restrict__ C)
{
    __shared__ __align__(128) char smem[4 * TILE_B];   // 40 KB

    const uint32_t sAh = smem_u32(smem);
    const uint32_t sAl = sAh + TILE_B;
    const uint32_t sWh = sAh + 2 * TILE_B;
    const uint32_t sWl = sAh + 3 * TILE_B;

    const int t    = threadIdx.x;
    const int warp = t >> 5;
    const int lane = t & 31;
    const int bm   = blockIdx.y * 128;
    const int bn   = blockIdx.x * 128;
    const int wm   = (warp & 3) * 32;   // warp m offset
    const int wn   = (warp >> 2) * 64;  // warp n offset

    // Per-thread load mapping: 4 float4 per operand per chunk
    int lrow[4], lc4[4];
#pragma unroll
    for (int j = 0; j < 4; j++) {
        int idx = j * 256 + t;          // 0..1023 float4 slots
        lrow[j] = idx >> 3;             // 8 float4 per 32-float row
        lc4[j]  = (idx & 7) << 2;
    }

    // ldmatrix lane addressing (byte offsets within a tile)
    // A (x4): lanes 0-15 -> rows 0-15, lanes 16-31 -> same rows, +16B in k
    const uint32_t a_off = (uint32_t)(wm + (lane & 15)) * ROWB + ((lane >> 4) << 4);
    // W (x4): n = (lane>>4)*8 + (lane&7); k half from bit3
    const uint32_t w_off =
        (uint32_t)(wn + ((lane >> 4) << 3) + (lane & 7)) * ROWB + (((lane >> 3) & 1) << 4);

    float acc[2][8][4];
#pragma unroll
    for (int mt = 0; mt < 2; mt++)
#pragma unroll
        for (int nt = 0; nt < 8; nt++)
#pragma unroll
            for (int i = 0; i < 4; i++) acc[mt][nt][i] = 0.f;

    // Preload chunk 0
    float4 pa[4], pw[4];
#pragma unroll
    for (int j = 0; j < 4; j++) {
        pa[j] = *(const float4*)(A + (size_t)(bm + lrow[j]) * D_ + lc4[j]);
        pw[j] = *(const float4*)(W + (size_t)(bn + lrow[j]) * D_ + lc4[j]);
    }

#pragma unroll 1
    for (int ch = 0; ch < D_ / 32; ch++) {
        // Stage current chunk into smem (split convert)
#pragma unroll
        for (int j = 0; j < 4; j++) {
            uint32_t soff = (uint32_t)lrow[j] * ROWB + lc4[j] * 2;
            cvt_split_sts(pa[j], sAh + soff, sAl + soff);
            cvt_split_sts(pw[j], sWh + soff, sWl + soff);
        }
        __syncthreads();

        // Prefetch next chunk (LDG issues early, hidden behind MMAs)
        if (ch + 1 < D_ / 32) {
            const int k0 = (ch + 1) * 32;
#pragma unroll
            for (int j = 0; j < 4; j++) {
                pa[j] = *(const float4*)(A + (size_t)(bm + lrow[j]) * D_ + k0 + lc4[j]);
                pw[j] = *(const float4*)(W + (size_t)(bn + lrow[j]) * D_ + k0 + lc4[j]);
            }
        }

        // Two K=16 steps
#pragma unroll
        for (int s = 0; s < 2; s++) {
            const uint32_t ks = s * 32;   // 16 bf16 = 32 bytes

            uint32_t ah[2][4], al[2][4];
            LDSM4(ah[0], sAh + a_off + ks);
            LDSM4(ah[1], sAh + a_off + 16 * ROWB + ks);
            LDSM4(al[0], sAl + a_off + ks);
            LDSM4(al[1], sAl + a_off + 16 * ROWB + ks);

            uint32_t wh[4][4], wl[4][4];
#pragma unroll
            for (int g = 0; g < 4; g++) {
                LDSM4(wh[g], sWh + w_off + (uint32_t)g * 16 * ROWB + ks);
                LDSM4(wl[g], sWl + w_off + (uint32_t)g * 16 * ROWB + ks);
            }

#pragma unroll
            for (int mt = 0; mt < 2; mt++) {
#pragma unroll
                for (int nt = 0; nt < 8; nt++) {
                    uint32_t* bh = &wh[nt >> 1][(nt & 1) * 2];
                    uint32_t* bl = &wl[nt >> 1][(nt & 1) * 2];
                    MMA16816(acc[mt][nt], ah[mt], bh);
                    MMA16816(acc[mt][nt], al[mt], bh);
                    MMA16816(acc[mt][nt], ah[mt], bl);
                }
            }
        }
        __syncthreads();
    }

    // Epilogue: direct register -> gmem (float2 per acc pair), bias (+sigmoid)
    const int er0 = bm + wm + (lane >> 2);
    const int ec0 = bn + wn + (lane & 3) * 2;

    float2 bb[8];
#pragma unroll
    for (int nt = 0; nt < 8; nt++)
        bb[nt] = *(const float2*)&bias[ec0 + nt * 8];

#pragma unroll
    for (int mt = 0; mt < 2; mt++) {
#pragma unroll
        for (int nt = 0; nt < 8; nt++) {
#pragma unroll
            for (int h = 0; h < 2; h++) {   // h=0: row, h=1: row+8
                float2 v;
                v.x = acc[mt][nt][h * 2 + 0] + bb[nt].x;
                v.y = acc[mt][nt][h * 2 + 1] + bb[nt].y;
                if (SIG) {
                    v.x = 1.f / (1.f + __expf(-v.x));
                    v.y = 1.f / (1.f + __expf(-v.y));
                }
                *(float2*)(C + (size_t)(er0 + mt * 16 + h * 8) * D_ + ec0 + nt * 8) = v;
            }
        }
    }
}

// ---------------------------------------------------------------------------
// Fused "attention" middle stage (unchanged). One block per s.
// ---------------------------------------------------------------------------
#define ES_STRIDE 68
#define ES_PER_B  (64 * ES_STRIDE)
#define VS_PER_B  (16 * ES_STRIDE)
#define SMEM_FLOATS (8 * ES_PER_B + 16384)

__global__ void __launch_bounds__(256) attn_kernel()
{
    extern __shared__ float smf[];
    float* ES = smf;
    float* R  = smf + 8 * ES_PER_B;

    const int s = blockIdx.x;
    const int t = threadIdx.x;

    for (int f = t; f < 8 * 256; f += 256) {
        const int b  = f >> 8;
        const int d4 = f & 255;
        const size_t g = ((size_t)b * S_ + s) * 256 + d4;
        ((float4*)R)[f]          = ((const float4*)g_Q)[g];
        ((float4*)(R + 8192))[f] = ((const float4*)g_K)[g];
    }
    __syncthreads();

    const float* Qs = R;
    const float* Ks = R + 8192;
    const int tp = (t >> 4) * 4;
    const int tq = (t & 15) * 4;

    float sacc[4][4];
#pragma unroll
    for (int i = 0; i < 4; i++)
#pragma unroll
        for (int j = 0; j < 4; j++) sacc[i][j] = 0.f;

    for (int b = 0; b < 8; b++) {
        const float* Qb = Qs + b * 1024;
        const float* Kb = Ks + b * 1024;
        float acc[4][4];
#pragma unroll
        for (int i = 0; i < 4; i++)
#pragma unroll
            for (int j = 0; j < 4; j++) acc[i][j] = 0.f;

#pragma unroll
        for (int h = 0; h < 16; h++) {
            float4 q4 = *(const float4*)(Qb + h * 64 + tp);
            float4 k4 = *(const float4*)(Kb + h * 64 + tq);
            float qa[4] = {q4.x, q4.y, q4.z, q4.w};
            float ka[4] = {k4.x, k4.y, k4.z, k4.w};
#pragma unroll
            for (int i = 0; i < 4; i++)
#pragma unroll
                for (int j = 0; j < 4; j++)
                    acc[i][j] += qa[i] * ka[j];
        }
        float* ESb = ES + b * ES_PER_B;
#pragma unroll
        for (int i = 0; i < 4; i++) {
            float4 e;
            e.x = __expf(acc[i][0] * 0.125f);
            e.y = __expf(acc[i][1] * 0.125f);
            e.z = __expf(acc[i][2] * 0.125f);
            e.w = __expf(acc[i][3] * 0.125f);
            sacc[i][0] += e.x; sacc[i][1] += e.y;
            sacc[i][2] += e.z; sacc[i][3] += e.w;
            *(float4*)&ESb[(tp + i) * ES_STRIDE + tq] = e;
        }
    }

    float rd[4][4];
#pragma unroll
    for (int i = 0; i < 4; i++)
#pragma unroll
        for (int j = 0; j < 4; j++) rd[i][j] = 1.f / sacc[i][j];

    for (int b = 0; b < 8; b++) {
        float* ESb = ES + b * ES_PER_B;
#pragma unroll
        for (int i = 0; i < 4; i++) {
            float4 e = *(const float4*)&ESb[(tp + i) * ES_STRIDE + tq];
            e.x *= rd[i][0]; e.y *= rd[i][1];
            e.z *= rd[i][2]; e.w *= rd[i][3];
            *(float4*)&ESb[(tp + i) * ES_STRIDE + tq] = e;
        }
    }
    __syncthreads();

    for (int f = t; f < 8 * 256; f += 256) {
        const int b  = f >> 8;
        const int d4 = f & 255;
        const size_t g = ((size_t)b * S_ + s) * 256 + d4;
        float4 v = ((const float4*)g_V)[g];
        const int d = d4 * 4;
        const int h = d >> 6;
        const int q = d & 63;
        float* Vb = R + b * VS_PER_B + h * ES_STRIDE + q;
        Vb[0] = v.x; Vb[1] = v.y; Vb[2] = v.z; Vb[3] = v.w;
    }
    __syncthreads();

    for (int b = 0; b < 8; b++) {
        const float* ESb = ES + b * ES_PER_B;
        const float* Vb  = R + b * VS_PER_B;
        for (int o = t; o < 1024; o += 256) {
            const int h = o >> 6;
            const int p = o & 63;
            const float* er = ESb + p * ES_STRIDE;
            const float* vr = Vb + h * ES_STRIDE;
            float a = 0.f;
#pragma unroll
            for (int q = 0; q < 64; q += 4) {
                float4 e4 = *(const float4*)(er + q);
                float4 v4 = *(const float4*)(vr + q);
                a += e4.x * v4.x + e4.y * v4.y + e4.z * v4.z + e4.w * v4.w;
            }
            g_A[((size_t)b * S_ + s) * D_ + h * 64 + p] = a;
        }
    }
}

// ---------------------------------------------------------------------------
extern "C" void kernel_launch(void* const* d_in, const int* in_sizes, int n_in,
                              void* d_out, int out_size)
{
    const float* query = (const float*)d_in[0];
    const float* key   = (const float*)d_in[1];
    const float* value = (const float*)d_in[2];
    const float* Wq    = (const float*)d_in[3];
    const float* bq    = (const float*)d_in[4];
    const float* Wk    = (const float*)d_in[5];
    const float* bk    = (const float*)d_in[6];
    const float* Wv    = (const float*)d_in[7];
    const float* bv    = (const float*)d_in[8];
    const float* Wo    = (const float*)d_in[9];
    const float* bo    = (const float*)d_in[10];
    float* out = (float*)d_out;

    float *gQ, *gK, *gV, *gA;
    cudaGetSymbolAddress((void**)&gQ, g_Q);
    cudaGetSymbolAddress((void**)&gK, g_K);
    cudaGetSymbolAddress((void**)&gV, g_V);
    cudaGetSymbolAddress((void**)&gA, g_A);

    dim3 grid(D_ / 128, M_TOT / 128);   // (8, 64)
    gemm_tc<0><<<grid, 256>>>(query, Wq, bq, gQ);
    gemm_tc<0><<<grid, 256>>>(key,   Wk, bk, gK);
    gemm_tc<0><<<grid, 256>>>(value, Wv, bv, gV);

    const size_t smem = SMEM_FLOATS * sizeof(float);   // 200 KB
    cudaFuncSetAttribute(attn_kernel,
                         cudaFuncAttributeMaxDynamicSharedMemorySize, (int)smem);
    attn_kernel<<<S_, 256, smem>>>();

    gemm_tc<1><<<grid, 256>>>(gA, Wo, bo, out);
}

// round 5
// speedup vs baseline: 2.2301x; 1.0123x over previous
#include <cuda_runtime.h>
#include <cuda_bf16.h>
#include <cstdint>

// Problem constants
#define B_ 8
#define S_ 1024
#define D_ 1024
#define M_TOT (B_ * S_)   // 8192

// Scratch (allocation-free rule: __device__ globals)
__device__ float g_Q[B_ * S_ * D_];
__device__ float g_K[B_ * S_ * D_];
__device__ float g_V[B_ * S_ * D_];
__device__ float g_A[B_ * S_ * D_];

// ---------------------------------------------------------------------------
// Warp-level tensor-core helpers (base-target PTX: ldmatrix + mma.sync HMMA)
// ---------------------------------------------------------------------------
__device__ __forceinline__ uint32_t smem_u32(const void* p) {
    uint32_t a;
    asm("{ .reg .u64 t; cvta.to.shared.u64 t, %1; cvt.u32.u64 %0, t; }"
        : "=r"(a) : "l"(p));
    return a;
}

#define LDSM4(r, addr)                                                        \
    asm volatile("ldmatrix.sync.aligned.m8n8.x4.shared.b16 "                  \
                 "{%0, %1, %2, %3}, [%4];"                                    \
                 : "=r"((r)[0]), "=r"((r)[1]), "=r"((r)[2]), "=r"((r)[3])     \
                 : "r"(addr))

#define MMA16816(d, a, b)                                                     \
    asm volatile("mma.sync.aligned.m16n8k16.row.col.f32.bf16.bf16.f32 "       \
                 "{%0, %1, %2, %3}, {%4, %5, %6, %7}, {%8, %9}, "             \
                 "{%0, %1, %2, %3};"                                          \
                 : "+f"((d)[0]), "+f"((d)[1]), "+f"((d)[2]), "+f"((d)[3])     \
                 : "r"((a)[0]), "r"((a)[1]), "r"((a)[2]), "r"((a)[3]),        \
                   "r"((b)[0]), "r"((b)[1]))

// Split a float4 into bf16-hi + bf16-lo and store both (8B STS each)
__device__ __forceinline__ void cvt_split_sts(float4 v, uint32_t hi_addr,
                                              uint32_t lo_addr) {
    uint32_t h01, h23;
    asm("cvt.rn.bf16x2.f32 %0, %1, %2;" : "=r"(h01) : "f"(v.y), "f"(v.x));
    asm("cvt.rn.bf16x2.f32 %0, %1, %2;" : "=r"(h23) : "f"(v.w), "f"(v.z));
    float hx = __uint_as_float(h01 << 16);
    float hy = __uint_as_float(h01 & 0xffff0000u);
    float hz = __uint_as_float(h23 << 16);
    float hw = __uint_as_float(h23 & 0xffff0000u);
    uint32_t l01, l23;
    asm("cvt.rn.bf16x2.f32 %0, %1, %2;" : "=r"(l01) : "f"(v.y - hy), "f"(v.x - hx));
    asm("cvt.rn.bf16x2.f32 %0, %1, %2;" : "=r"(l23) : "f"(v.w - hw), "f"(v.z - hz));
    asm volatile("st.shared.v2.b32 [%0], {%1, %2};"
                 :: "r"(hi_addr), "r"(h01), "r"(h23) : "memory");
    asm volatile("st.shared.v2.b32 [%0], {%1, %2};"
                 :: "r"(lo_addr), "r"(l01), "r"(l23) : "memory");
}

// ---------------------------------------------------------------------------
// Split-bf16 HMMA GEMM (NT), double-buffered pipeline.
// BM=BN=128, BK=32, 256 threads (8 warps, 4m x 2n), warp tile 32x64.
// Stage = 4 bf16 tiles (Ah/Al/Wh/Wl), 128 rows x 32 cols, row stride 80B.
// One __syncthreads per chunk; STS(next) overlaps MMA(cur) between k-steps.
// ---------------------------------------------------------------------------
#define ROWB 80                       // bytes per smem row (32 bf16 + pad)
#define TILE_B (128 * ROWB)           // 10240 bytes per tile
#define STAGE_B (4 * TILE_B)          // 40960 bytes per stage
#define GEMM_SMEM (2 * STAGE_B)       // 81920 bytes

template <int SIG>
__global__ void __launch_bounds__(256) gemm_tc(
    const float* __restrict__ A, const float* __restrict__ W,
    const float* __restrict__ bias, float* __restrict__ C)
{
    extern __shared__ __align__(128) char dsm[];
    const uint32_t s0 = smem_u32(dsm);

    const int t    = threadIdx.x;
    const int warp = t >> 5;
    const int lane = t & 31;
    const int bm   = blockIdx.y * 128;
    const int bn   = blockIdx.x * 128;
    const int wm   = (warp & 3) * 32;   // warp m offset
    const int wn   = (warp >> 2) * 64;  // warp n offset

    // Per-thread load mapping: 4 float4 per operand per chunk
    int lrow[4], lc4[4];
#pragma unroll
    for (int j = 0; j < 4; j++) {
        int idx = j * 256 + t;          // 0..1023 float4 slots
        lrow[j] = idx >> 3;             // 8 float4 per 32-float row
        lc4[j]  = (idx & 7) << 2;
    }

    // ldmatrix lane addressing (byte offsets within a tile)
    const uint32_t a_off = (uint32_t)(wm + (lane & 15)) * ROWB + ((lane >> 4) << 4);
    const uint32_t w_off =
        (uint32_t)(wn + ((lane >> 4) << 3) + (lane & 7)) * ROWB + (((lane >> 3) & 1) << 4);

    float acc[2][8][4];
#pragma unroll
    for (int mt = 0; mt < 2; mt++)
#pragma unroll
        for (int nt = 0; nt < 8; nt++)
#pragma unroll
            for (int i = 0; i < 4; i++) acc[mt][nt][i] = 0.f;

    float4 pa[4], pw[4];
    // Preload + stage chunk 0
#pragma unroll
    for (int j = 0; j < 4; j++) {
        pa[j] = *(const float4*)(A + (size_t)(bm + lrow[j]) * D_ + lc4[j]);
        pw[j] = *(const float4*)(W + (size_t)(bn + lrow[j]) * D_ + lc4[j]);
    }
#pragma unroll
    for (int j = 0; j < 4; j++) {
        uint32_t soff = (uint32_t)lrow[j] * ROWB + lc4[j] * 2;
        cvt_split_sts(pa[j], s0 + soff,              s0 + TILE_B + soff);
        cvt_split_sts(pw[j], s0 + 2 * TILE_B + soff, s0 + 3 * TILE_B + soff);
    }
    __syncthreads();

#pragma unroll 1
    for (int ch = 0; ch < D_ / 32; ch++) {
        const uint32_t cur = s0 + (uint32_t)(ch & 1) * STAGE_B;
        const uint32_t nxt = s0 + (uint32_t)((ch + 1) & 1) * STAGE_B;
        const bool have_next = (ch + 1 < D_ / 32);

        // Issue next chunk's LDGs first (latency covered by MMA block below)
        if (have_next) {
            const int k0 = (ch + 1) * 32;
#pragma unroll
            for (int j = 0; j < 4; j++) {
                pa[j] = *(const float4*)(A + (size_t)(bm + lrow[j]) * D_ + k0 + lc4[j]);
                pw[j] = *(const float4*)(W + (size_t)(bn + lrow[j]) * D_ + k0 + lc4[j]);
            }
        }

        const uint32_t cAh = cur, cAl = cur + TILE_B;
        const uint32_t cWh = cur + 2 * TILE_B, cWl = cur + 3 * TILE_B;

        // ---- k-step 0 ----
        {
            uint32_t ah[2][4], al[2][4];
            LDSM4(ah[0], cAh + a_off);
            LDSM4(ah[1], cAh + a_off + 16 * ROWB);
            LDSM4(al[0], cAl + a_off);
            LDSM4(al[1], cAl + a_off + 16 * ROWB);
            uint32_t wh[4][4], wl[4][4];
#pragma unroll
            for (int g = 0; g < 4; g++) {
                LDSM4(wh[g], cWh + w_off + (uint32_t)g * 16 * ROWB);
                LDSM4(wl[g], cWl + w_off + (uint32_t)g * 16 * ROWB);
            }
#pragma unroll
            for (int mt = 0; mt < 2; mt++)
#pragma unroll
                for (int nt = 0; nt < 8; nt++) {
                    uint32_t* bh = &wh[nt >> 1][(nt & 1) * 2];
                    uint32_t* bl = &wl[nt >> 1][(nt & 1) * 2];
                    MMA16816(acc[mt][nt], ah[mt], bh);
                    MMA16816(acc[mt][nt], al[mt], bh);
                    MMA16816(acc[mt][nt], ah[mt], bl);
                }
        }

        // Stage next chunk into the other buffer (overlaps MMA issue)
        if (have_next) {
#pragma unroll
            for (int j = 0; j < 4; j++) {
                uint32_t soff = (uint32_t)lrow[j] * ROWB + lc4[j] * 2;
                cvt_split_sts(pa[j], nxt + soff,              nxt + TILE_B + soff);
                cvt_split_sts(pw[j], nxt + 2 * TILE_B + soff, nxt + 3 * TILE_B + soff);
            }
        }

        // ---- k-step 1 ----
        {
            uint32_t ah[2][4], al[2][4];
            LDSM4(ah[0], cAh + a_off + 32);
            LDSM4(ah[1], cAh + a_off + 16 * ROWB + 32);
            LDSM4(al[0], cAl + a_off + 32);
            LDSM4(al[1], cAl + a_off + 16 * ROWB + 32);
            uint32_t wh[4][4], wl[4][4];
#pragma unroll
            for (int g = 0; g < 4; g++) {
                LDSM4(wh[g], cWh + w_off + (uint32_t)g * 16 * ROWB + 32);
                LDSM4(wl[g], cWl + w_off + (uint32_t)g * 16 * ROWB + 32);
            }
#pragma unroll
            for (int mt = 0; mt < 2; mt++)
#pragma unroll
                for (int nt = 0; nt < 8; nt++) {
                    uint32_t* bh = &wh[nt >> 1][(nt & 1) * 2];
                    uint32_t* bl = &wl[nt >> 1][(nt & 1) * 2];
                    MMA16816(acc[mt][nt], ah[mt], bh);
                    MMA16816(acc[mt][nt], al[mt], bh);
                    MMA16816(acc[mt][nt], ah[mt], bl);
                }
        }
        __syncthreads();
    }

    // Epilogue: direct register -> gmem (float2 per acc pair), bias (+sigmoid)
    const int er0 = bm + wm + (lane >> 2);
    const int ec0 = bn + wn + (lane & 3) * 2;

    float2 bb[8];
#pragma unroll
    for (int nt = 0; nt < 8; nt++)
        bb[nt] = *(const float2*)&bias[ec0 + nt * 8];

#pragma unroll
    for (int mt = 0; mt < 2; mt++) {
#pragma unroll
        for (int nt = 0; nt < 8; nt++) {
#pragma unroll
            for (int h = 0; h < 2; h++) {
                float2 v;
                v.x = acc[mt][nt][h * 2 + 0] + bb[nt].x;
                v.y = acc[mt][nt][h * 2 + 1] + bb[nt].y;
                if (SIG) {
                    v.x = 1.f / (1.f + __expf(-v.x));
                    v.y = 1.f / (1.f + __expf(-v.y));
                }
                *(float2*)(C + (size_t)(er0 + mt * 16 + h * 8) * D_ + ec0 + nt * 8) = v;
            }
        }
    }
}

// ---------------------------------------------------------------------------
// Fused "attention" middle stage. 512 threads, b-split warp-groups:
// group g (threads g*256..) handles batches 4g..4g+3 with 4x4 score tiles.
// Batch-softmax denominators exchanged through a reused smem strip.
// ---------------------------------------------------------------------------
#define ES_STRIDE 68
#define ES_PER_B  (64 * ES_STRIDE)
#define VS_PER_B  (16 * ES_STRIDE)
#define V_BASE    4352                       // V region offset inside R
#define SMEM_FLOATS (8 * ES_PER_B + 16384)   // 200 KB

__global__ void __launch_bounds__(512) attn_kernel()
{
    extern __shared__ float smf[];
    float* ES = smf;
    float* R  = smf + 8 * ES_PER_B;

    const int s  = blockIdx.x;
    const int t  = threadIdx.x;
    const int tg = t >> 8;        // warp-group: 0 -> b 0..3, 1 -> b 4..7
    const int tt = t & 255;

    // Load Q,K rows for all 8 batches at this s (coalesced float4)
    for (int f = t; f < 8 * 256; f += 512) {
        const int b  = f >> 8;
        const int d4 = f & 255;
        const size_t g = ((size_t)b * S_ + s) * 256 + d4;
        ((float4*)R)[f]          = ((const float4*)g_Q)[g];
        ((float4*)(R + 8192))[f] = ((const float4*)g_K)[g];
    }
    __syncthreads();

    const float* Qs = R;
    const float* Ks = R + 8192;
    const int tp = (tt >> 4) * 4;
    const int tq = (tt & 15) * 4;
    const int b0 = tg * 4;

    float sacc[4][4];
#pragma unroll
    for (int i = 0; i < 4; i++)
#pragma unroll
        for (int j = 0; j < 4; j++) sacc[i][j] = 0.f;

    // Pass 1: exp-scores for this group's 4 batches, partial denominators
#pragma unroll
    for (int bb = 0; bb < 4; bb++) {
        const int b = b0 + bb;
        const float* Qb = Qs + b * 1024;
        const float* Kb = Ks + b * 1024;
        float acc[4][4];
#pragma unroll
        for (int i = 0; i < 4; i++)
#pragma unroll
            for (int j = 0; j < 4; j++) acc[i][j] = 0.f;

#pragma unroll
        for (int h = 0; h < 16; h++) {
            float4 q4 = *(const float4*)(Qb + h * 64 + tp);
            float4 k4 = *(const float4*)(Kb + h * 64 + tq);
            float qa[4] = {q4.x, q4.y, q4.z, q4.w};
            float ka[4] = {k4.x, k4.y, k4.z, k4.w};
#pragma unroll
            for (int i = 0; i < 4; i++)
#pragma unroll
                for (int j = 0; j < 4; j++)
                    acc[i][j] += qa[i] * ka[j];
        }
        float* ESb = ES + b * ES_PER_B;
#pragma unroll
        for (int i = 0; i < 4; i++) {
            float4 e;
            e.x = __expf(acc[i][0] * 0.125f);
            e.y = __expf(acc[i][1] * 0.125f);
            e.z = __expf(acc[i][2] * 0.125f);
            e.w = __expf(acc[i][3] * 0.125f);
            sacc[i][0] += e.x; sacc[i][1] += e.y;
            sacc[i][2] += e.z; sacc[i][3] += e.w;
            *(float4*)&ESb[(tp + i) * ES_STRIDE + tq] = e;
        }
    }
    __syncthreads();   // Q/K reads done; R[0..4351] reusable as exchange strip

    // Denominator exchange between the two groups via P = R[0..4351]
    float* P = R;
    if (tg == 0) {
#pragma unroll
        for (int i = 0; i < 4; i++)
            *(float4*)&P[(tp + i) * ES_STRIDE + tq] =
                make_float4(sacc[i][0], sacc[i][1], sacc[i][2], sacc[i][3]);
    }
    __syncthreads();

    float rd[4][4];
    if (tg == 1) {
#pragma unroll
        for (int i = 0; i < 4; i++) {
            float4 o = *(const float4*)&P[(tp + i) * ES_STRIDE + tq];
            rd[i][0] = 1.f / (o.x + sacc[i][0]);
            rd[i][1] = 1.f / (o.y + sacc[i][1]);
            rd[i][2] = 1.f / (o.z + sacc[i][2]);
            rd[i][3] = 1.f / (o.w + sacc[i][3]);
        }
        __syncthreads();   // group0's partial reads... (all threads reach below)
#pragma unroll
        for (int i = 0; i < 4; i++)
            *(float4*)&P[(tp + i) * ES_STRIDE + tq] =
                make_float4(rd[i][0], rd[i][1], rd[i][2], rd[i][3]);
    } else {
        __syncthreads();
    }
    __syncthreads();
    if (tg == 0) {
#pragma unroll
        for (int i = 0; i < 4; i++) {
            float4 r4 = *(const float4*)&P[(tp + i) * ES_STRIDE + tq];
            rd[i][0] = r4.x; rd[i][1] = r4.y; rd[i][2] = r4.z; rd[i][3] = r4.w;
        }
    }

    // Normalize this group's ES in place
#pragma unroll
    for (int bb = 0; bb < 4; bb++) {
        float* ESb = ES + (b0 + bb) * ES_PER_B;
#pragma unroll
        for (int i = 0; i < 4; i++) {
            float4 e = *(const float4*)&ESb[(tp + i) * ES_STRIDE + tq];
            e.x *= rd[i][0]; e.y *= rd[i][1];
            e.z *= rd[i][2]; e.w *= rd[i][3];
            *(float4*)&ESb[(tp + i) * ES_STRIDE + tq] = e;
        }
    }
    __syncthreads();   // rd reads from P done -> V may overwrite R

    // Load V (stride-68 padded layout at R + V_BASE)
    for (int f = t; f < 8 * 256; f += 512) {
        const int b  = f >> 8;
        const int d4 = f & 255;
        const size_t g = ((size_t)b * S_ + s) * 256 + d4;
        float4 v = ((const float4*)g_V)[g];
        const int d = d4 * 4;
        const int h = d >> 6;
        const int q = d & 63;
        float* Vb = R + V_BASE + b * VS_PER_B + h * ES_STRIDE + q;
        Vb[0] = v.x; Vb[1] = v.y; Vb[2] = v.z; Vb[3] = v.w;
    }
    __syncthreads();

    // Pass 2 (b-split): out[b,p,h] = sum_q attn[b,p,q] * V[b,h,q]
#pragma unroll
    for (int bb = 0; bb < 4; bb++) {
        const int b = b0 + bb;
        const float* ESb = ES + b * ES_PER_B;
        const float* Vb  = R + V_BASE + b * VS_PER_B;
        for (int o = tt; o < 1024; o += 256) {
            const int h = o >> 6;
            const int p = o & 63;
            const float* er = ESb + p * ES_STRIDE;
            const float* vr = Vb + h * ES_STRIDE;
            float a = 0.f;
#pragma unroll
            for (int q = 0; q < 64; q += 4) {
                float4 e4 = *(const float4*)(er + q);
                float4 v4 = *(const float4*)(vr + q);
                a += e4.x * v4.x + e4.y * v4.y + e4.z * v4.z + e4.w * v4.w;
            }
            g_A[((size_t)b * S_ + s) * D_ + h * 64 + p] = a;
        }
    }
}

// ---------------------------------------------------------------------------
extern "C" void kernel_launch(void* const* d_in, const int* in_sizes, int n_in,
                              void* d_out, int out_size)
{
    const float* query = (const float*)d_in[0];
    const float* key   = (const float*)d_in[1];
    const float* value = (const float*)d_in[2];
    const float* Wq    = (const float*)d_in[3];
    const float* bq    = (const float*)d_in[4];
    const float* Wk    = (const float*)d_in[5];
    const float* bk    = (const float*)d_in[6];
    const float* Wv    = (const float*)d_in[7];
    const float* bv    = (const float*)d_in[8];
    const float* Wo    = (const float*)d_in[9];
    const float* bo    = (const float*)d_in[10];
    float* out = (float*)d_out;

    float *gQ, *gK, *gV, *gA;
    cudaGetSymbolAddress((void**)&gQ, g_Q);
    cudaGetSymbolAddress((void**)&gK, g_K);
    cudaGetSymbolAddress((void**)&gV, g_V);
    cudaGetSymbolAddress((void**)&gA, g_A);

    cudaFuncSetAttribute(gemm_tc<0>,
                         cudaFuncAttributeMaxDynamicSharedMemorySize, GEMM_SMEM);
    cudaFuncSetAttribute(gemm_tc<1>,
                         cudaFuncAttributeMaxDynamicSharedMemorySize, GEMM_SMEM);

    dim3 grid(D_ / 128, M_TOT / 128);   // (8, 64)
    gemm_tc<0><<<grid, 256, GEMM_SMEM>>>(query, Wq, bq, gQ);
    gemm_tc<0><<<grid, 256, GEMM_SMEM>>>(key,   Wk, bk, gK);
    gemm_tc<0><<<grid, 256, GEMM_SMEM>>>(value, Wv, bv, gV);

    const size_t smem = SMEM_FLOATS * sizeof(float);   // 200 KB
    cudaFuncSetAttribute(attn_kernel,
                         cudaFuncAttributeMaxDynamicSharedMemorySize, (int)smem);
    attn_kernel<<<S_, 512, smem>>>();

    gemm_tc<1><<<grid, 256, GEMM_SMEM>>>(gA, Wo, bo, out);
}

// round 6
// speedup vs baseline: 2.4284x; 1.0889x over previous
#include <cuda_runtime.h>
#include <cuda_bf16.h>
#include <cstdint>

// Problem constants
#define B_ 8
#define S_ 1024
#define D_ 1024
#define M_TOT (B_ * S_)   // 8192

// Scratch (allocation-free rule: __device__ globals)
__device__ float g_Q[B_ * S_ * D_];
__device__ float g_K[B_ * S_ * D_];
__device__ float g_V[B_ * S_ * D_];
__device__ float g_A[B_ * S_ * D_];

// ---------------------------------------------------------------------------
// Warp-level tensor-core helpers (base-target PTX: ldmatrix + mma.sync HMMA)
// ---------------------------------------------------------------------------
__device__ __forceinline__ uint32_t smem_u32(const void* p) {
    uint32_t a;
    asm("{ .reg .u64 t; cvta.to.shared.u64 t, %1; cvt.u32.u64 %0, t; }"
        : "=r"(a) : "l"(p));
    return a;
}

#define LDSM4(r, addr)                                                        \
    asm volatile("ldmatrix.sync.aligned.m8n8.x4.shared.b16 "                  \
                 "{%0, %1, %2, %3}, [%4];"                                    \
                 : "=r"((r)[0]), "=r"((r)[1]), "=r"((r)[2]), "=r"((r)[3])     \
                 : "r"(addr))

#define MMA16816(d, a, b)                                                     \
    asm volatile("mma.sync.aligned.m16n8k16.row.col.f32.bf16.bf16.f32 "       \
                 "{%0, %1, %2, %3}, {%4, %5, %6, %7}, {%8, %9}, "             \
                 "{%0, %1, %2, %3};"                                          \
                 : "+f"((d)[0]), "+f"((d)[1]), "+f"((d)[2]), "+f"((d)[3])     \
                 : "r"((a)[0]), "r"((a)[1]), "r"((a)[2]), "r"((a)[3]),        \
                   "r"((b)[0]), "r"((b)[1]))

// Split a float4 into bf16-hi + bf16-lo and store both (8B STS each)
__device__ __forceinline__ void cvt_split_sts(float4 v, uint32_t hi_addr,
                                              uint32_t lo_addr) {
    uint32_t h01, h23;
    asm("cvt.rn.bf16x2.f32 %0, %1, %2;" : "=r"(h01) : "f"(v.y), "f"(v.x));
    asm("cvt.rn.bf16x2.f32 %0, %1, %2;" : "=r"(h23) : "f"(v.w), "f"(v.z));
    float hx = __uint_as_float(h01 << 16);
    float hy = __uint_as_float(h01 & 0xffff0000u);
    float hz = __uint_as_float(h23 << 16);
    float hw = __uint_as_float(h23 & 0xffff0000u);
    uint32_t l01, l23;
    asm("cvt.rn.bf16x2.f32 %0, %1, %2;" : "=r"(l01) : "f"(v.y - hy), "f"(v.x - hx));
    asm("cvt.rn.bf16x2.f32 %0, %1, %2;" : "=r"(l23) : "f"(v.w - hw), "f"(v.z - hz));
    asm volatile("st.shared.v2.b32 [%0], {%1, %2};"
                 :: "r"(hi_addr), "r"(h01), "r"(h23) : "memory");
    asm volatile("st.shared.v2.b32 [%0], {%1, %2};"
                 :: "r"(lo_addr), "r"(l01), "r"(l23) : "memory");
}

// ---------------------------------------------------------------------------
// Split-bf16 HMMA GEMM (NT), double-buffered, 512 threads (16 warps, 4m x 4n).
// BM=BN=128, BK=32, warp tile 32x32 (2 m-tiles x 4 n-tiles, acc=32 regs).
// Stage = 4 bf16 tiles (Ah/Al/Wh/Wl), 128 rows x 32 cols, row stride 80B
// (conflict-free ldmatrix: banks 20r mod 32 tile perfectly).
// 3 MMA passes per k-step: Ah*Wh + Al*Wh + Ah*Wl  (lo*lo dropped, ~2^-16).
// ---------------------------------------------------------------------------
#define ROWB 80                       // bytes per smem row (32 bf16 + pad)
#define TILE_B (128 * ROWB)           // 10240 bytes per tile
#define STAGE_B (4 * TILE_B)          // 40960 bytes per stage
#define GEMM_SMEM (2 * STAGE_B)       // 81920 bytes

template <int SIG>
__global__ void __launch_bounds__(512) gemm_tc(
    const float* __restrict__ A, const float* __restrict__ W,
    const float* __restrict__ bias, float* __restrict__ C)
{
    extern __shared__ __align__(128) char dsm[];
    const uint32_t s0 = smem_u32(dsm);

    const int t    = threadIdx.x;
    const int warp = t >> 5;
    const int lane = t & 31;
    const int bm   = blockIdx.y * 128;
    const int bn   = blockIdx.x * 128;
    const int wm   = (warp & 3) * 32;   // warp m offset
    const int wn   = (warp >> 2) * 32;  // warp n offset

    // Per-thread load mapping: 2 float4 per operand per chunk
    int lrow[2], lc4[2];
#pragma unroll
    for (int j = 0; j < 2; j++) {
        int idx = j * 512 + t;          // 0..1023 float4 slots
        lrow[j] = idx >> 3;             // 8 float4 per 32-float row
        lc4[j]  = (idx & 7) << 2;
    }

    // ldmatrix lane addressing (byte offsets within a tile)
    const uint32_t a_off = (uint32_t)(wm + (lane & 15)) * ROWB + ((lane >> 4) << 4);
    const uint32_t w_off =
        (uint32_t)(wn + ((lane >> 4) << 3) + (lane & 7)) * ROWB + (((lane >> 3) & 1) << 4);

    float acc[2][4][4];
#pragma unroll
    for (int mt = 0; mt < 2; mt++)
#pragma unroll
        for (int nt = 0; nt < 4; nt++)
#pragma unroll
            for (int i = 0; i < 4; i++) acc[mt][nt][i] = 0.f;

    float4 pa[2], pw[2];
    // Preload + stage chunk 0
#pragma unroll
    for (int j = 0; j < 2; j++) {
        pa[j] = *(const float4*)(A + (size_t)(bm + lrow[j]) * D_ + lc4[j]);
        pw[j] = *(const float4*)(W + (size_t)(bn + lrow[j]) * D_ + lc4[j]);
    }
#pragma unroll
    for (int j = 0; j < 2; j++) {
        uint32_t soff = (uint32_t)lrow[j] * ROWB + lc4[j] * 2;
        cvt_split_sts(pa[j], s0 + soff,              s0 + TILE_B + soff);
        cvt_split_sts(pw[j], s0 + 2 * TILE_B + soff, s0 + 3 * TILE_B + soff);
    }
    __syncthreads();

#pragma unroll 1
    for (int ch = 0; ch < D_ / 32; ch++) {
        const uint32_t cur = s0 + (uint32_t)(ch & 1) * STAGE_B;
        const uint32_t nxt = s0 + (uint32_t)((ch + 1) & 1) * STAGE_B;
        const bool have_next = (ch + 1 < D_ / 32);

        // Issue next chunk's LDGs first (latency covered by MMA block below)
        if (have_next) {
            const int k0 = (ch + 1) * 32;
#pragma unroll
            for (int j = 0; j < 2; j++) {
                pa[j] = *(const float4*)(A + (size_t)(bm + lrow[j]) * D_ + k0 + lc4[j]);
                pw[j] = *(const float4*)(W + (size_t)(bn + lrow[j]) * D_ + k0 + lc4[j]);
            }
        }

        const uint32_t cAh = cur, cAl = cur + TILE_B;
        const uint32_t cWh = cur + 2 * TILE_B, cWl = cur + 3 * TILE_B;

        // ---- k-step 0 ----
        {
            uint32_t ah[2][4], al[2][4], wh[2][4], wl[2][4];
            LDSM4(ah[0], cAh + a_off);
            LDSM4(ah[1], cAh + a_off + 16 * ROWB);
            LDSM4(al[0], cAl + a_off);
            LDSM4(al[1], cAl + a_off + 16 * ROWB);
            LDSM4(wh[0], cWh + w_off);
            LDSM4(wh[1], cWh + w_off + 16 * ROWB);
            LDSM4(wl[0], cWl + w_off);
            LDSM4(wl[1], cWl + w_off + 16 * ROWB);
#pragma unroll
            for (int mt = 0; mt < 2; mt++)
#pragma unroll
                for (int nt = 0; nt < 4; nt++) {
                    uint32_t* bh = &wh[nt >> 1][(nt & 1) * 2];
                    uint32_t* bl = &wl[nt >> 1][(nt & 1) * 2];
                    MMA16816(acc[mt][nt], ah[mt], bh);
                    MMA16816(acc[mt][nt], al[mt], bh);
                    MMA16816(acc[mt][nt], ah[mt], bl);
                }
        }

        // Stage next chunk into the other buffer (overlaps MMA issue)
        if (have_next) {
#pragma unroll
            for (int j = 0; j < 2; j++) {
                uint32_t soff = (uint32_t)lrow[j] * ROWB + lc4[j] * 2;
                cvt_split_sts(pa[j], nxt + soff,              nxt + TILE_B + soff);
                cvt_split_sts(pw[j], nxt + 2 * TILE_B + soff, nxt + 3 * TILE_B + soff);
            }
        }

        // ---- k-step 1 ----
        {
            uint32_t ah[2][4], al[2][4], wh[2][4], wl[2][4];
            LDSM4(ah[0], cAh + a_off + 32);
            LDSM4(ah[1], cAh + a_off + 16 * ROWB + 32);
            LDSM4(al[0], cAl + a_off + 32);
            LDSM4(al[1], cAl + a_off + 16 * ROWB + 32);
            LDSM4(wh[0], cWh + w_off + 32);
            LDSM4(wh[1], cWh + w_off + 16 * ROWB + 32);
            LDSM4(wl[0], cWl + w_off + 32);
            LDSM4(wl[1], cWl + w_off + 16 * ROWB + 32);
#pragma unroll
            for (int mt = 0; mt < 2; mt++)
#pragma unroll
                for (int nt = 0; nt < 4; nt++) {
                    uint32_t* bh = &wh[nt >> 1][(nt & 1) * 2];
                    uint32_t* bl = &wl[nt >> 1][(nt & 1) * 2];
                    MMA16816(acc[mt][nt], ah[mt], bh);
                    MMA16816(acc[mt][nt], al[mt], bh);
                    MMA16816(acc[mt][nt], ah[mt], bl);
                }
        }
        __syncthreads();
    }

    // Epilogue: direct register -> gmem (float2 per acc pair), bias (+sigmoid)
    const int er0 = bm + wm + (lane >> 2);
    const int ec0 = bn + wn + (lane & 3) * 2;

    float2 bb[4];
#pragma unroll
    for (int nt = 0; nt < 4; nt++)
        bb[nt] = *(const float2*)&bias[ec0 + nt * 8];

#pragma unroll
    for (int mt = 0; mt < 2; mt++) {
#pragma unroll
        for (int nt = 0; nt < 4; nt++) {
#pragma unroll
            for (int h = 0; h < 2; h++) {
                float2 v;
                v.x = acc[mt][nt][h * 2 + 0] + bb[nt].x;
                v.y = acc[mt][nt][h * 2 + 1] + bb[nt].y;
                if (SIG) {
                    v.x = 1.f / (1.f + __expf(-v.x));
                    v.y = 1.f / (1.f + __expf(-v.y));
                }
                *(float2*)(C + (size_t)(er0 + mt * 16 + h * 8) * D_ + ec0 + nt * 8) = v;
            }
        }
    }
}

// ---------------------------------------------------------------------------
// Fused "attention" middle stage. 512 threads, b-split warp-groups:
// group g (threads g*256..) handles batches 4g..4g+3 with 4x4 score tiles.
// Batch-softmax denominators exchanged through a reused smem strip.
// ---------------------------------------------------------------------------
#define ES_STRIDE 68
#define ES_PER_B  (64 * ES_STRIDE)
#define VS_PER_B  (16 * ES_STRIDE)
#define V_BASE    4352                       // V region offset inside R
#define SMEM_FLOATS (8 * ES_PER_B + 16384)   // 200 KB

__global__ void __launch_bounds__(512) attn_kernel()
{
    extern __shared__ float smf[];
    float* ES = smf;
    float* R  = smf + 8 * ES_PER_B;

    const int s  = blockIdx.x;
    const int t  = threadIdx.x;
    const int tg = t >> 8;        // warp-group: 0 -> b 0..3, 1 -> b 4..7
    const int tt = t & 255;

    // Load Q,K rows for all 8 batches at this s (coalesced float4)
    for (int f = t; f < 8 * 256; f += 512) {
        const int b  = f >> 8;
        const int d4 = f & 255;
        const size_t g = ((size_t)b * S_ + s) * 256 + d4;
        ((float4*)R)[f]          = ((const float4*)g_Q)[g];
        ((float4*)(R + 8192))[f] = ((const float4*)g_K)[g];
    }
    __syncthreads();

    const float* Qs = R;
    const float* Ks = R + 8192;
    const int tp = (tt >> 4) * 4;
    const int tq = (tt & 15) * 4;
    const int b0 = tg * 4;

    float sacc[4][4];
#pragma unroll
    for (int i = 0; i < 4; i++)
#pragma unroll
        for (int j = 0; j < 4; j++) sacc[i][j] = 0.f;

    // Pass 1: exp-scores for this group's 4 batches, partial denominators
#pragma unroll
    for (int bb = 0; bb < 4; bb++) {
        const int b = b0 + bb;
        const float* Qb = Qs + b * 1024;
        const float* Kb = Ks + b * 1024;
        float acc[4][4];
#pragma unroll
        for (int i = 0; i < 4; i++)
#pragma unroll
            for (int j = 0; j < 4; j++) acc[i][j] = 0.f;

#pragma unroll
        for (int h = 0; h < 16; h++) {
            float4 q4 = *(const float4*)(Qb + h * 64 + tp);
            float4 k4 = *(const float4*)(Kb + h * 64 + tq);
            float qa[4] = {q4.x, q4.y, q4.z, q4.w};
            float ka[4] = {k4.x, k4.y, k4.z, k4.w};
#pragma unroll
            for (int i = 0; i < 4; i++)
#pragma unroll
                for (int j = 0; j < 4; j++)
                    acc[i][j] += qa[i] * ka[j];
        }
        float* ESb = ES + b * ES_PER_B;
#pragma unroll
        for (int i = 0; i < 4; i++) {
            float4 e;
            e.x = __expf(acc[i][0] * 0.125f);
            e.y = __expf(acc[i][1] * 0.125f);
            e.z = __expf(acc[i][2] * 0.125f);
            e.w = __expf(acc[i][3] * 0.125f);
            sacc[i][0] += e.x; sacc[i][1] += e.y;
            sacc[i][2] += e.z; sacc[i][3] += e.w;
            *(float4*)&ESb[(tp + i) * ES_STRIDE + tq] = e;
        }
    }
    __syncthreads();   // Q/K reads done; R[0..4351] reusable as exchange strip

    // Denominator exchange between the two groups via P = R[0..4351]
    float* P = R;
    if (tg == 0) {
#pragma unroll
        for (int i = 0; i < 4; i++)
            *(float4*)&P[(tp + i) * ES_STRIDE + tq] =
                make_float4(sacc[i][0], sacc[i][1], sacc[i][2], sacc[i][3]);
    }
    __syncthreads();

    float rd[4][4];
    if (tg == 1) {
#pragma unroll
        for (int i = 0; i < 4; i++) {
            float4 o = *(const float4*)&P[(tp + i) * ES_STRIDE + tq];
            rd[i][0] = 1.f / (o.x + sacc[i][0]);
            rd[i][1] = 1.f / (o.y + sacc[i][1]);
            rd[i][2] = 1.f / (o.z + sacc[i][2]);
            rd[i][3] = 1.f / (o.w + sacc[i][3]);
        }
        __syncthreads();
#pragma unroll
        for (int i = 0; i < 4; i++)
            *(float4*)&P[(tp + i) * ES_STRIDE + tq] =
                make_float4(rd[i][0], rd[i][1], rd[i][2], rd[i][3]);
    } else {
        __syncthreads();
    }
    __syncthreads();
    if (tg == 0) {
#pragma unroll
        for (int i = 0; i < 4; i++) {
            float4 r4 = *(const float4*)&P[(tp + i) * ES_STRIDE + tq];
            rd[i][0] = r4.x; rd[i][1] = r4.y; rd[i][2] = r4.z; rd[i][3] = r4.w;
        }
    }

    // Normalize this group's ES in place
#pragma unroll
    for (int bb = 0; bb < 4; bb++) {
        float* ESb = ES + (b0 + bb) * ES_PER_B;
#pragma unroll
        for (int i = 0; i < 4; i++) {
            float4 e = *(const float4*)&ESb[(tp + i) * ES_STRIDE + tq];
            e.x *= rd[i][0]; e.y *= rd[i][1];
            e.z *= rd[i][2]; e.w *= rd[i][3];
            *(float4*)&ESb[(tp + i) * ES_STRIDE + tq] = e;
        }
    }
    __syncthreads();   // rd reads from P done -> V may overwrite R

    // Load V (stride-68 padded layout at R + V_BASE)
    for (int f = t; f < 8 * 256; f += 512) {
        const int b  = f >> 8;
        const int d4 = f & 255;
        const size_t g = ((size_t)b * S_ + s) * 256 + d4;
        float4 v = ((const float4*)g_V)[g];
        const int d = d4 * 4;
        const int h = d >> 6;
        const int q = d & 63;
        float* Vb = R + V_BASE + b * VS_PER_B + h * ES_STRIDE + q;
        Vb[0] = v.x; Vb[1] = v.y; Vb[2] = v.z; Vb[3] = v.w;
    }
    __syncthreads();

    // Pass 2 (b-split): out[b,p,h] = sum_q attn[b,p,q] * V[b,h,q]
#pragma unroll
    for (int bb = 0; bb < 4; bb++) {
        const int b = b0 + bb;
        const float* ESb = ES + b * ES_PER_B;
        const float* Vb  = R + V_BASE + b * VS_PER_B;
        for (int o = tt; o < 1024; o += 256) {
            const int h = o >> 6;
            const int p = o & 63;
            const float* er = ESb + p * ES_STRIDE;
            const float* vr = Vb + h * ES_STRIDE;
            float a = 0.f;
#pragma unroll
            for (int q = 0; q < 64; q += 4) {
                float4 e4 = *(const float4*)(er + q);
                float4 v4 = *(const float4*)(vr + q);
                a += e4.x * v4.x + e4.y * v4.y + e4.z * v4.z + e4.w * v4.w;
            }
            g_A[((size_t)b * S_ + s) * D_ + h * 64 + p] = a;
        }
    }
}

// ---------------------------------------------------------------------------
extern "C" void kernel_launch(void* const* d_in, const int* in_sizes, int n_in,
                              void* d_out, int out_size)
{
    const float* query = (const float*)d_in[0];
    const float* key   = (const float*)d_in[1];
    const float* value = (const float*)d_in[2];
    const float* Wq    = (const float*)d_in[3];
    const float* bq    = (const float*)d_in[4];
    const float* Wk    = (const float*)d_in[5];
    const float* bk    = (const float*)d_in[6];
    const float* Wv    = (const float*)d_in[7];
    const float* bv    = (const float*)d_in[8];
    const float* Wo    = (const float*)d_in[9];
    const float* bo    = (const float*)d_in[10];
    float* out = (float*)d_out;

    float *gQ, *gK, *gV, *gA;
    cudaGetSymbolAddress((void**)&gQ, g_Q);
    cudaGetSymbolAddress((void**)&gK, g_K);
    cudaGetSymbolAddress((void**)&gV, g_V);
    cudaGetSymbolAddress((void**)&gA, g_A);

    cudaFuncSetAttribute(gemm_tc<0>,
                         cudaFuncAttributeMaxDynamicSharedMemorySize, GEMM_SMEM);
    cudaFuncSetAttribute(gemm_tc<1>,
                         cudaFuncAttributeMaxDynamicSharedMemorySize, GEMM_SMEM);

    dim3 grid(D_ / 128, M_TOT / 128);   // (8, 64)
    gemm_tc<0><<<grid, 512, GEMM_SMEM>>>(query, Wq, bq, gQ);
    gemm_tc<0><<<grid, 512, GEMM_SMEM>>>(key,   Wk, bk, gK);
    gemm_tc<0><<<grid, 512, GEMM_SMEM>>>(value, Wv, bv, gV);

    const size_t smem = SMEM_FLOATS * sizeof(float);   // 200 KB
    cudaFuncSetAttribute(attn_kernel,
                         cudaFuncAttributeMaxDynamicSharedMemorySize, (int)smem);
    attn_kernel<<<S_, 512, smem>>>();

    gemm_tc<1><<<grid, 512, GEMM_SMEM>>>(gA, Wo, bo, out);
}

// round 7
// speedup vs baseline: 3.1151x; 1.2827x over previous
#include <cuda_runtime.h>
#include <cuda_fp16.h>
#include <cstdint>

// Problem constants
#define B_ 8
#define S_ 1024
#define D_ 1024
#define M_TOT (B_ * S_)   // 8192

// Scratch (allocation-free rule: __device__ globals)
__device__ float g_Q[B_ * S_ * D_];
__device__ float g_K[B_ * S_ * D_];
__device__ float g_V[B_ * S_ * D_];
__device__ float g_A[B_ * S_ * D_];

// ---------------------------------------------------------------------------
// Warp-level tensor-core helpers (base-target PTX: ldmatrix + mma.sync HMMA)
// ---------------------------------------------------------------------------
__device__ __forceinline__ uint32_t smem_u32(const void* p) {
    uint32_t a;
    asm("{ .reg .u64 t; cvta.to.shared.u64 t, %1; cvt.u32.u64 %0, t; }"
        : "=r"(a) : "l"(p));
    return a;
}

#define LDSM4(r, addr)                                                        \
    asm volatile("ldmatrix.sync.aligned.m8n8.x4.shared.b16 "                  \
                 "{%0, %1, %2, %3}, [%4];"                                    \
                 : "=r"((r)[0]), "=r"((r)[1]), "=r"((r)[2]), "=r"((r)[3])     \
                 : "r"(addr))

#define MMA16816F16(d, a, b)                                                  \
    asm volatile("mma.sync.aligned.m16n8k16.row.col.f32.f16.f16.f32 "         \
                 "{%0, %1, %2, %3}, {%4, %5, %6, %7}, {%8, %9}, "             \
                 "{%0, %1, %2, %3};"                                          \
                 : "+f"((d)[0]), "+f"((d)[1]), "+f"((d)[2]), "+f"((d)[3])     \
                 : "r"((a)[0]), "r"((a)[1]), "r"((a)[2]), "r"((a)[3]),        \
                   "r"((b)[0]), "r"((b)[1]))

// Convert float4 -> 4 fp16 and store (8B STS)
__device__ __forceinline__ void cvt_sts(float4 v, uint32_t addr) {
    uint32_t p01, p23;
    asm("cvt.rn.f16x2.f32 %0, %1, %2;" : "=r"(p01) : "f"(v.y), "f"(v.x));
    asm("cvt.rn.f16x2.f32 %0, %1, %2;" : "=r"(p23) : "f"(v.w), "f"(v.z));
    asm volatile("st.shared.v2.b32 [%0], {%1, %2};"
                 :: "r"(addr), "r"(p01), "r"(p23) : "memory");
}

// ---------------------------------------------------------------------------
// fp16 single-pass HMMA GEMM (NT), double-buffered, 512 threads (16 warps,
// 4m x 4n). BM=BN=128, BK=32, warp tile 32x32 (2 m-tiles x 4 n-tiles).
// Stage = 2 fp16 tiles (A / W), 128 rows x 32 cols, row stride 80B
// (conflict-free ldmatrix: banks 20r mod 32 tile perfectly).
// ---------------------------------------------------------------------------
#define ROWB 80                       // bytes per smem row (32 fp16 + pad)
#define TILE_B (128 * ROWB)           // 10240 bytes per tile
#define STAGE_B (2 * TILE_B)          // 20480 bytes per stage
#define GEMM_SMEM (2 * STAGE_B)       // 40960 bytes

template <int SIG>
__global__ void __launch_bounds__(512) gemm_tc(
    const float* __restrict__ A, const float* __restrict__ W,
    const float* __restrict__ bias, float* __restrict__ C)
{
    extern __shared__ __align__(128) char dsm[];
    const uint32_t s0 = smem_u32(dsm);

    const int t    = threadIdx.x;
    const int warp = t >> 5;
    const int lane = t & 31;
    const int bm   = blockIdx.y * 128;
    const int bn   = blockIdx.x * 128;
    const int wm   = (warp & 3) * 32;   // warp m offset
    const int wn   = (warp >> 2) * 32;  // warp n offset

    // Per-thread load mapping: 2 float4 per operand per chunk
    int lrow[2], lc4[2];
#pragma unroll
    for (int j = 0; j < 2; j++) {
        int idx = j * 512 + t;          // 0..1023 float4 slots
        lrow[j] = idx >> 3;             // 8 float4 per 32-float row
        lc4[j]  = (idx & 7) << 2;
    }

    // ldmatrix lane addressing (byte offsets within a tile)
    const uint32_t a_off = (uint32_t)(wm + (lane & 15)) * ROWB + ((lane >> 4) << 4);
    const uint32_t w_off =
        (uint32_t)(wn + ((lane >> 4) << 3) + (lane & 7)) * ROWB + (((lane >> 3) & 1) << 4);

    float acc[2][4][4];
#pragma unroll
    for (int mt = 0; mt < 2; mt++)
#pragma unroll
        for (int nt = 0; nt < 4; nt++)
#pragma unroll
            for (int i = 0; i < 4; i++) acc[mt][nt][i] = 0.f;

    float4 pa[2], pw[2];
    // Preload + stage chunk 0
#pragma unroll
    for (int j = 0; j < 2; j++) {
        pa[j] = *(const float4*)(A + (size_t)(bm + lrow[j]) * D_ + lc4[j]);
        pw[j] = *(const float4*)(W + (size_t)(bn + lrow[j]) * D_ + lc4[j]);
    }
#pragma unroll
    for (int j = 0; j < 2; j++) {
        uint32_t soff = (uint32_t)lrow[j] * ROWB + lc4[j] * 2;
        cvt_sts(pa[j], s0 + soff);
        cvt_sts(pw[j], s0 + TILE_B + soff);
    }
    __syncthreads();

#pragma unroll 1
    for (int ch = 0; ch < D_ / 32; ch++) {
        const uint32_t cur = s0 + (uint32_t)(ch & 1) * STAGE_B;
        const uint32_t nxt = s0 + (uint32_t)((ch + 1) & 1) * STAGE_B;
        const bool have_next = (ch + 1 < D_ / 32);

        // Issue next chunk's LDGs first (latency covered by MMA block below)
        if (have_next) {
            const int k0 = (ch + 1) * 32;
#pragma unroll
            for (int j = 0; j < 2; j++) {
                pa[j] = *(const float4*)(A + (size_t)(bm + lrow[j]) * D_ + k0 + lc4[j]);
                pw[j] = *(const float4*)(W + (size_t)(bn + lrow[j]) * D_ + k0 + lc4[j]);
            }
        }

        const uint32_t cA = cur, cW = cur + TILE_B;

        // ---- k-step 0 ----
        {
            uint32_t av[2][4], wv[2][4];
            LDSM4(av[0], cA + a_off);
            LDSM4(av[1], cA + a_off + 16 * ROWB);
            LDSM4(wv[0], cW + w_off);
            LDSM4(wv[1], cW + w_off + 16 * ROWB);
#pragma unroll
            for (int mt = 0; mt < 2; mt++)
#pragma unroll
                for (int nt = 0; nt < 4; nt++)
                    MMA16816F16(acc[mt][nt], av[mt], (&wv[nt >> 1][(nt & 1) * 2]));
        }

        // Stage next chunk into the other buffer (overlaps MMA issue)
        if (have_next) {
#pragma unroll
            for (int j = 0; j < 2; j++) {
                uint32_t soff = (uint32_t)lrow[j] * ROWB + lc4[j] * 2;
                cvt_sts(pa[j], nxt + soff);
                cvt_sts(pw[j], nxt + TILE_B + soff);
            }
        }

        // ---- k-step 1 ----
        {
            uint32_t av[2][4], wv[2][4];
            LDSM4(av[0], cA + a_off + 32);
            LDSM4(av[1], cA + a_off + 16 * ROWB + 32);
            LDSM4(wv[0], cW + w_off + 32);
            LDSM4(wv[1], cW + w_off + 16 * ROWB + 32);
#pragma unroll
            for (int mt = 0; mt < 2; mt++)
#pragma unroll
                for (int nt = 0; nt < 4; nt++)
                    MMA16816F16(acc[mt][nt], av[mt], (&wv[nt >> 1][(nt & 1) * 2]));
        }
        __syncthreads();
    }

    // Epilogue: direct register -> gmem (float2 per acc pair), bias (+sigmoid)
    const int er0 = bm + wm + (lane >> 2);
    const int ec0 = bn + wn + (lane & 3) * 2;

    float2 bb[4];
#pragma unroll
    for (int nt = 0; nt < 4; nt++)
        bb[nt] = *(const float2*)&bias[ec0 + nt * 8];

#pragma unroll
    for (int mt = 0; mt < 2; mt++) {
#pragma unroll
        for (int nt = 0; nt < 4; nt++) {
#pragma unroll
            for (int h = 0; h < 2; h++) {
                float2 v;
                v.x = acc[mt][nt][h * 2 + 0] + bb[nt].x;
                v.y = acc[mt][nt][h * 2 + 1] + bb[nt].y;
                if (SIG) {
                    v.x = 1.f / (1.f + __expf(-v.x));
                    v.y = 1.f / (1.f + __expf(-v.y));
                }
                *(float2*)(C + (size_t)(er0 + mt * 16 + h * 8) * D_ + ec0 + nt * 8) = v;
            }
        }
    }
}

// ---------------------------------------------------------------------------
// Fused "attention" middle stage (unchanged from R6). 512 threads, b-split.
// ---------------------------------------------------------------------------
#define ES_STRIDE 68
#define ES_PER_B  (64 * ES_STRIDE)
#define VS_PER_B  (16 * ES_STRIDE)
#define V_BASE    4352                       // V region offset inside R
#define SMEM_FLOATS (8 * ES_PER_B + 16384)   // 200 KB

__global__ void __launch_bounds__(512) attn_kernel()
{
    extern __shared__ float smf[];
    float* ES = smf;
    float* R  = smf + 8 * ES_PER_B;

    const int s  = blockIdx.x;
    const int t  = threadIdx.x;
    const int tg = t >> 8;        // warp-group: 0 -> b 0..3, 1 -> b 4..7
    const int tt = t & 255;

    // Load Q,K rows for all 8 batches at this s (coalesced float4)
    for (int f = t; f < 8 * 256; f += 512) {
        const int b  = f >> 8;
        const int d4 = f & 255;
        const size_t g = ((size_t)b * S_ + s) * 256 + d4;
        ((float4*)R)[f]          = ((const float4*)g_Q)[g];
        ((float4*)(R + 8192))[f] = ((const float4*)g_K)[g];
    }
    __syncthreads();

    const float* Qs = R;
    const float* Ks = R + 8192;
    const int tp = (tt >> 4) * 4;
    const int tq = (tt & 15) * 4;
    const int b0 = tg * 4;

    float sacc[4][4];
#pragma unroll
    for (int i = 0; i < 4; i++)
#pragma unroll
        for (int j = 0; j < 4; j++) sacc[i][j] = 0.f;

    // Pass 1: exp-scores for this group's 4 batches, partial denominators
#pragma unroll
    for (int bb = 0; bb < 4; bb++) {
        const int b = b0 + bb;
        const float* Qb = Qs + b * 1024;
        const float* Kb = Ks + b * 1024;
        float acc[4][4];
#pragma unroll
        for (int i = 0; i < 4; i++)
#pragma unroll
            for (int j = 0; j < 4; j++) acc[i][j] = 0.f;

#pragma unroll
        for (int h = 0; h < 16; h++) {
            float4 q4 = *(const float4*)(Qb + h * 64 + tp);
            float4 k4 = *(const float4*)(Kb + h * 64 + tq);
            float qa[4] = {q4.x, q4.y, q4.z, q4.w};
            float ka[4] = {k4.x, k4.y, k4.z, k4.w};
#pragma unroll
            for (int i = 0; i < 4; i++)
#pragma unroll
                for (int j = 0; j < 4; j++)
                    acc[i][j] += qa[i] * ka[j];
        }
        float* ESb = ES + b * ES_PER_B;
#pragma unroll
        for (int i = 0; i < 4; i++) {
            float4 e;
            e.x = __expf(acc[i][0] * 0.125f);
            e.y = __expf(acc[i][1] * 0.125f);
            e.z = __expf(acc[i][2] * 0.125f);
            e.w = __expf(acc[i][3] * 0.125f);
            sacc[i][0] += e.x; sacc[i][1] += e.y;
            sacc[i][2] += e.z; sacc[i][3] += e.w;
            *(float4*)&ESb[(tp + i) * ES_STRIDE + tq] = e;
        }
    }
    __syncthreads();   // Q/K reads done; R[0..4351] reusable as exchange strip

    // Denominator exchange between the two groups via P = R[0..4351]
    float* P = R;
    if (tg == 0) {
#pragma unroll
        for (int i = 0; i < 4; i++)
            *(float4*)&P[(tp + i) * ES_STRIDE + tq] =
                make_float4(sacc[i][0], sacc[i][1], sacc[i][2], sacc[i][3]);
    }
    __syncthreads();

    float rd[4][4];
    if (tg == 1) {
#pragma unroll
        for (int i = 0; i < 4; i++) {
            float4 o = *(const float4*)&P[(tp + i) * ES_STRIDE + tq];
            rd[i][0] = 1.f / (o.x + sacc[i][0]);
            rd[i][1] = 1.f / (o.y + sacc[i][1]);
            rd[i][2] = 1.f / (o.z + sacc[i][2]);
            rd[i][3] = 1.f / (o.w + sacc[i][3]);
        }
        __syncthreads();
#pragma unroll
        for (int i = 0; i < 4; i++)
            *(float4*)&P[(tp + i) * ES_STRIDE + tq] =
                make_float4(rd[i][0], rd[i][1], rd[i][2], rd[i][3]);
    } else {
        __syncthreads();
    }
    __syncthreads();
    if (tg == 0) {
#pragma unroll
        for (int i = 0; i < 4; i++) {
            float4 r4 = *(const float4*)&P[(tp + i) * ES_STRIDE + tq];
            rd[i][0] = r4.x; rd[i][1] = r4.y; rd[i][2] = r4.z; rd[i][3] = r4.w;
        }
    }

    // Normalize this group's ES in place
#pragma unroll
    for (int bb = 0; bb < 4; bb++) {
        float* ESb = ES + (b0 + bb) * ES_PER_B;
#pragma unroll
        for (int i = 0; i < 4; i++) {
            float4 e = *(const float4*)&ESb[(tp + i) * ES_STRIDE + tq];
            e.x *= rd[i][0]; e.y *= rd[i][1];
            e.z *= rd[i][2]; e.w *= rd[i][3];
            *(float4*)&ESb[(tp + i) * ES_STRIDE + tq] = e;
        }
    }
    __syncthreads();   // rd reads from P done -> V may overwrite R

    // Load V (stride-68 padded layout at R + V_BASE)
    for (int f = t; f < 8 * 256; f += 512) {
        const int b  = f >> 8;
        const int d4 = f & 255;
        const size_t g = ((size_t)b * S_ + s) * 256 + d4;
        float4 v = ((const float4*)g_V)[g];
        const int d = d4 * 4;
        const int h = d >> 6;
        const int q = d & 63;
        float* Vb = R + V_BASE + b * VS_PER_B + h * ES_STRIDE + q;
        Vb[0] = v.x; Vb[1] = v.y; Vb[2] = v.z; Vb[3] = v.w;
    }
    __syncthreads();

    // Pass 2 (b-split): out[b,p,h] = sum_q attn[b,p,q] * V[b,h,q]
#pragma unroll
    for (int bb = 0; bb < 4; bb++) {
        const int b = b0 + bb;
        const float* ESb = ES + b * ES_PER_B;
        const float* Vb  = R + V_BASE + b * VS_PER_B;
        for (int o = tt; o < 1024; o += 256) {
            const int h = o >> 6;
            const int p = o & 63;
            const float* er = ESb + p * ES_STRIDE;
            const float* vr = Vb + h * ES_STRIDE;
            float a = 0.f;
#pragma unroll
            for (int q = 0; q < 64; q += 4) {
                float4 e4 = *(const float4*)(er + q);
                float4 v4 = *(const float4*)(vr + q);
                a += e4.x * v4.x + e4.y * v4.y + e4.z * v4.z + e4.w * v4.w;
            }
            g_A[((size_t)b * S_ + s) * D_ + h * 64 + p] = a;
        }
    }
}

// ---------------------------------------------------------------------------
extern "C" void kernel_launch(void* const* d_in, const int* in_sizes, int n_in,
                              void* d_out, int out_size)
{
    const float* query = (const float*)d_in[0];
    const float* key   = (const float*)d_in[1];
    const float* value = (const float*)d_in[2];
    const float* Wq    = (const float*)d_in[3];
    const float* bq    = (const float*)d_in[4];
    const float* Wk    = (const float*)d_in[5];
    const float* bk    = (const float*)d_in[6];
    const float* Wv    = (const float*)d_in[7];
    const float* bv    = (const float*)d_in[8];
    const float* Wo    = (const float*)d_in[9];
    const float* bo    = (const float*)d_in[10];
    float* out = (float*)d_out;

    float *gQ, *gK, *gV, *gA;
    cudaGetSymbolAddress((void**)&gQ, g_Q);
    cudaGetSymbolAddress((void**)&gK, g_K);
    cudaGetSymbolAddress((void**)&gV, g_V);
    cudaGetSymbolAddress((void**)&gA, g_A);

    cudaFuncSetAttribute(gemm_tc<0>,
                         cudaFuncAttributeMaxDynamicSharedMemorySize, GEMM_SMEM);
    cudaFuncSetAttribute(gemm_tc<1>,
                         cudaFuncAttributeMaxDynamicSharedMemorySize, GEMM_SMEM);

    dim3 grid(D_ / 128, M_TOT / 128);   // (8, 64)
    gemm_tc<0><<<grid, 512, GEMM_SMEM>>>(query, Wq, bq, gQ);
    gemm_tc<0><<<grid, 512, GEMM_SMEM>>>(key,   Wk, bk, gK);
    gemm_tc<0><<<grid, 512, GEMM_SMEM>>>(value, Wv, bv, gV);

    const size_t smem = SMEM_FLOATS * sizeof(float);   // 200 KB
    cudaFuncSetAttribute(attn_kernel,
                         cudaFuncAttributeMaxDynamicSharedMemorySize, (int)smem);
    attn_kernel<<<S_, 512, smem>>>();

    gemm_tc<1><<<grid, 512, GEMM_SMEM>>>(gA, Wo, bo, out);
}

// round 8
// speedup vs baseline: 5.2157x; 1.6743x over previous
#include <cuda_runtime.h>
#include <cuda_fp16.h>
#include <cstdint>

// Problem constants
#define B_ 8
#define S_ 1024
#define D_ 1024
#define M_TOT (B_ * S_)   // 8192

// Scratch (allocation-free rule: __device__ globals)
__device__ float  g_Q[B_ * S_ * D_];
__device__ float  g_K[B_ * S_ * D_];
__device__ float  g_V[B_ * S_ * D_];
__device__ __half g_q16[B_ * S_ * D_];
__device__ __half g_k16[B_ * S_ * D_];
__device__ __half g_v16[B_ * S_ * D_];
__device__ __half g_a16[B_ * S_ * D_];
__device__ __half g_wq16[D_ * D_];
__device__ __half g_wk16[D_ * D_];
__device__ __half g_wv16[D_ * D_];
__device__ __half g_wo16[D_ * D_];

// ---------------------------------------------------------------------------
// Helpers
// ---------------------------------------------------------------------------
__device__ __forceinline__ uint32_t smem_u32(const void* p) {
    uint32_t a;
    asm("{ .reg .u64 t; cvta.to.shared.u64 t, %1; cvt.u32.u64 %0, t; }"
        : "=r"(a) : "l"(p));
    return a;
}

#define LDSM4(r, addr)                                                        \
    asm volatile("ldmatrix.sync.aligned.m8n8.x4.shared.b16 "                  \
                 "{%0, %1, %2, %3}, [%4];"                                    \
                 : "=r"((r)[0]), "=r"((r)[1]), "=r"((r)[2]), "=r"((r)[3])     \
                 : "r"(addr))

#define MMA16816F16(d, a, b)                                                  \
    asm volatile("mma.sync.aligned.m16n8k16.row.col.f32.f16.f16.f32 "         \
                 "{%0, %1, %2, %3}, {%4, %5, %6, %7}, {%8, %9}, "             \
                 "{%0, %1, %2, %3};"                                          \
                 : "+f"((d)[0]), "+f"((d)[1]), "+f"((d)[2]), "+f"((d)[3])     \
                 : "r"((a)[0]), "r"((a)[1]), "r"((a)[2]), "r"((a)[3]),        \
                   "r"((b)[0]), "r"((b)[1]))

#define CP_ASYNC16(dst, src)                                                  \
    asm volatile("cp.async.cg.shared.global [%0], [%1], 16;"                  \
                 :: "r"(dst), "l"(src) : "memory")
#define CP_COMMIT() asm volatile("cp.async.commit_group;" ::: "memory")
#define CP_WAIT2()  asm volatile("cp.async.wait_group 2;" ::: "memory")

// ---------------------------------------------------------------------------
// fp32 -> fp16 pre-conversion (elementwise, float4 -> 4x half)
// ---------------------------------------------------------------------------
__global__ void cvt16(const float4* __restrict__ in, uint2* __restrict__ out,
                      int n4)
{
    int i = blockIdx.x * blockDim.x + threadIdx.x;
    if (i < n4) {
        float4 v = in[i];
        uint32_t p01, p23;
        asm("cvt.rn.f16x2.f32 %0, %1, %2;" : "=r"(p01) : "f"(v.y), "f"(v.x));
        asm("cvt.rn.f16x2.f32 %0, %1, %2;" : "=r"(p23) : "f"(v.w), "f"(v.z));
        out[i] = make_uint2(p01, p23);
    }
}

// ---------------------------------------------------------------------------
// fp16 HMMA GEMM (NT), cp.async 4-stage pipeline, 512 threads (16 warps,
// 4m x 4n). BM=BN=128, BK=32, warp tile 32x32. A,W already fp16 in gmem.
// Stage = 2 fp16 tiles, 128 rows x 32 cols, row stride 80B (conflict-free
// ldmatrix: banks 20r mod 32 tile perfectly). One cp.async.128 per thread
// per tile per chunk; wait_group 2 keeps 3 chunks in flight.
// ---------------------------------------------------------------------------
#define ROWB 80                       // bytes per smem row (32 fp16 + pad)
#define TILE_B (128 * ROWB)           // 10240 bytes per tile
#define STAGE_B (2 * TILE_B)          // 20480 bytes per stage
#define NSTAGE 4
#define GEMM_SMEM (NSTAGE * STAGE_B)  // 81920 bytes
#define NCH (D_ / 32)                 // 32 chunks

template <int SIG>
__global__ void __launch_bounds__(512) gemm_tc(
    const __half* __restrict__ A, const __half* __restrict__ W,
    const float* __restrict__ bias, float* __restrict__ C)
{
    extern __shared__ __align__(128) char dsm[];
    const uint32_t s0 = smem_u32(dsm);

    const int t    = threadIdx.x;
    const int warp = t >> 5;
    const int lane = t & 31;
    const int bm   = blockIdx.y * 128;
    const int bn   = blockIdx.x * 128;
    const int wm   = (warp & 3) * 32;
    const int wn   = (warp >> 2) * 32;

    // cp.async mapping: one 16B copy per thread per tile
    const int crow = t >> 2;          // 0..127
    const int cseg = t & 3;           // 16B segment within 64B row
    const __half* gA = A + (size_t)(bm + crow) * D_ + cseg * 8;
    const __half* gW = W + (size_t)(bn + crow) * D_ + cseg * 8;
    const uint32_t cdst = (uint32_t)crow * ROWB + cseg * 16;

    // ldmatrix lane addressing
    const uint32_t a_off = (uint32_t)(wm + (lane & 15)) * ROWB + ((lane >> 4) << 4);
    const uint32_t w_off =
        (uint32_t)(wn + ((lane >> 4) << 3) + (lane & 7)) * ROWB + (((lane >> 3) & 1) << 4);

    float acc[2][4][4];
#pragma unroll
    for (int mt = 0; mt < 2; mt++)
#pragma unroll
        for (int nt = 0; nt < 4; nt++)
#pragma unroll
            for (int i = 0; i < 4; i++) acc[mt][nt][i] = 0.f;

    // Prologue: issue chunks 0..2
#pragma unroll
    for (int st = 0; st < NSTAGE - 1; st++) {
        const uint32_t sb = s0 + st * STAGE_B;
        CP_ASYNC16(sb + cdst,          gA + st * 32);
        CP_ASYNC16(sb + TILE_B + cdst, gW + st * 32);
        CP_COMMIT();
    }

#pragma unroll 1
    for (int ch = 0; ch < NCH; ch++) {
        CP_WAIT2();           // chunk ch resident
        __syncthreads();      // visible to all; stage (ch-1)&3 free

        // Issue chunk ch+3 into stage (ch+3)&3
        if (ch + NSTAGE - 1 < NCH) {
            const uint32_t sb = s0 + (uint32_t)((ch + NSTAGE - 1) & (NSTAGE - 1)) * STAGE_B;
            CP_ASYNC16(sb + cdst,          gA + (ch + NSTAGE - 1) * 32);
            CP_ASYNC16(sb + TILE_B + cdst, gW + (ch + NSTAGE - 1) * 32);
        }
        CP_COMMIT();          // always commit (empty groups keep accounting)

        const uint32_t cur = s0 + (uint32_t)(ch & (NSTAGE - 1)) * STAGE_B;
        const uint32_t cA = cur, cW = cur + TILE_B;

#pragma unroll
        for (int ks = 0; ks < 2; ks++) {
            const uint32_t ko = ks * 32;
            uint32_t av[2][4], wv[2][4];
            LDSM4(av[0], cA + a_off + ko);
            LDSM4(av[1], cA + a_off + 16 * ROWB + ko);
            LDSM4(wv[0], cW + w_off + ko);
            LDSM4(wv[1], cW + w_off + 16 * ROWB + ko);
#pragma unroll
            for (int mt = 0; mt < 2; mt++)
#pragma unroll
                for (int nt = 0; nt < 4; nt++)
                    MMA16816F16(acc[mt][nt], av[mt], (&wv[nt >> 1][(nt & 1) * 2]));
        }
    }

    // Epilogue: direct register -> gmem, bias (+sigmoid)
    const int er0 = bm + wm + (lane >> 2);
    const int ec0 = bn + wn + (lane & 3) * 2;

    float2 bb[4];
#pragma unroll
    for (int nt = 0; nt < 4; nt++)
        bb[nt] = *(const float2*)&bias[ec0 + nt * 8];

#pragma unroll
    for (int mt = 0; mt < 2; mt++) {
#pragma unroll
        for (int nt = 0; nt < 4; nt++) {
#pragma unroll
            for (int h = 0; h < 2; h++) {
                float2 v;
                v.x = acc[mt][nt][h * 2 + 0] + bb[nt].x;
                v.y = acc[mt][nt][h * 2 + 1] + bb[nt].y;
                if (SIG) {
                    v.x = 1.f / (1.f + __expf(-v.x));
                    v.y = 1.f / (1.f + __expf(-v.y));
                }
                *(float2*)(C + (size_t)(er0 + mt * 16 + h * 8) * D_ + ec0 + nt * 8) = v;
            }
        }
    }
}

// ---------------------------------------------------------------------------
// Fused "attention" middle stage. 512 threads, b-split warp-groups.
// Pass 2 register-tiled 4h x 4p (16 outputs/thread, 128 B LDS per output).
// Output written directly as fp16 (same quantization the Wo GEMM staging
// previously applied -> zero added error).
// ---------------------------------------------------------------------------
#define ES_STRIDE 68
#define ES_PER_B  (64 * ES_STRIDE)
#define VS_PER_B  (16 * ES_STRIDE)
#define V_BASE    4352                       // V region offset inside R
#define SMEM_FLOATS (8 * ES_PER_B + 16384)   // 200 KB

__global__ void __launch_bounds__(512) attn_kernel()
{
    extern __shared__ float smf[];
    float* ES = smf;
    float* R  = smf + 8 * ES_PER_B;

    const int s  = blockIdx.x;
    const int t  = threadIdx.x;
    const int tg = t >> 8;        // warp-group: 0 -> b 0..3, 1 -> b 4..7
    const int tt = t & 255;

    // Load Q,K rows for all 8 batches at this s (coalesced float4)
    for (int f = t; f < 8 * 256; f += 512) {
        const int b  = f >> 8;
        const int d4 = f & 255;
        const size_t g = ((size_t)b * S_ + s) * 256 + d4;
        ((float4*)R)[f]          = ((const float4*)g_Q)[g];
        ((float4*)(R + 8192))[f] = ((const float4*)g_K)[g];
    }
    __syncthreads();

    const float* Qs = R;
    const float* Ks = R + 8192;
    const int tp = (tt >> 4) * 4;
    const int tq = (tt & 15) * 4;
    const int b0 = tg * 4;

    float sacc[4][4];
#pragma unroll
    for (int i = 0; i < 4; i++)
#pragma unroll
        for (int j = 0; j < 4; j++) sacc[i][j] = 0.f;

    // Pass 1: exp-scores for this group's 4 batches, partial denominators
#pragma unroll
    for (int bb = 0; bb < 4; bb++) {
        const int b = b0 + bb;
        const float* Qb = Qs + b * 1024;
        const float* Kb = Ks + b * 1024;
        float acc[4][4];
#pragma unroll
        for (int i = 0; i < 4; i++)
#pragma unroll
            for (int j = 0; j < 4; j++) acc[i][j] = 0.f;

#pragma unroll
        for (int h = 0; h < 16; h++) {
            float4 q4 = *(const float4*)(Qb + h * 64 + tp);
            float4 k4 = *(const float4*)(Kb + h * 64 + tq);
            float qa[4] = {q4.x, q4.y, q4.z, q4.w};
            float ka[4] = {k4.x, k4.y, k4.z, k4.w};
#pragma unroll
            for (int i = 0; i < 4; i++)
#pragma unroll
                for (int j = 0; j < 4; j++)
                    acc[i][j] += qa[i] * ka[j];
        }
        float* ESb = ES + b * ES_PER_B;
#pragma unroll
        for (int i = 0; i < 4; i++) {
            float4 e;
            e.x = __expf(acc[i][0] * 0.125f);
            e.y = __expf(acc[i][1] * 0.125f);
            e.z = __expf(acc[i][2] * 0.125f);
            e.w = __expf(acc[i][3] * 0.125f);
            sacc[i][0] += e.x; sacc[i][1] += e.y;
            sacc[i][2] += e.z; sacc[i][3] += e.w;
            *(float4*)&ESb[(tp + i) * ES_STRIDE + tq] = e;
        }
    }
    __syncthreads();   // Q/K reads done; R reusable as exchange strip

    // Denominator exchange between the two groups via P = R[0..4351]
    float* P = R;
    if (tg == 0) {
#pragma unroll
        for (int i = 0; i < 4; i++)
            *(float4*)&P[(tp + i) * ES_STRIDE + tq] =
                make_float4(sacc[i][0], sacc[i][1], sacc[i][2], sacc[i][3]);
    }
    __syncthreads();

    float rd[4][4];
    if (tg == 1) {
#pragma unroll
        for (int i = 0; i < 4; i++) {
            float4 o = *(const float4*)&P[(tp + i) * ES_STRIDE + tq];
            rd[i][0] = 1.f / (o.x + sacc[i][0]);
            rd[i][1] = 1.f / (o.y + sacc[i][1]);
            rd[i][2] = 1.f / (o.z + sacc[i][2]);
            rd[i][3] = 1.f / (o.w + sacc[i][3]);
        }
        __syncthreads();
#pragma unroll
        for (int i = 0; i < 4; i++)
            *(float4*)&P[(tp + i) * ES_STRIDE + tq] =
                make_float4(rd[i][0], rd[i][1], rd[i][2], rd[i][3]);
    } else {
        __syncthreads();
    }
    __syncthreads();
    if (tg == 0) {
#pragma unroll
        for (int i = 0; i < 4; i++) {
            float4 r4 = *(const float4*)&P[(tp + i) * ES_STRIDE + tq];
            rd[i][0] = r4.x; rd[i][1] = r4.y; rd[i][2] = r4.z; rd[i][3] = r4.w;
        }
    }

    // Normalize this group's ES in place
#pragma unroll
    for (int bb = 0; bb < 4; bb++) {
        float* ESb = ES + (b0 + bb) * ES_PER_B;
#pragma unroll
        for (int i = 0; i < 4; i++) {
            float4 e = *(const float4*)&ESb[(tp + i) * ES_STRIDE + tq];
            e.x *= rd[i][0]; e.y *= rd[i][1];
            e.z *= rd[i][2]; e.w *= rd[i][3];
            *(float4*)&ESb[(tp + i) * ES_STRIDE + tq] = e;
        }
    }
    __syncthreads();   // rd reads from P done -> V may overwrite R

    // Load V (stride-68 padded layout at R + V_BASE)
    for (int f = t; f < 8 * 256; f += 512) {
        const int b  = f >> 8;
        const int d4 = f & 255;
        const size_t g = ((size_t)b * S_ + s) * 256 + d4;
        float4 v = ((const float4*)g_V)[g];
        const int d = d4 * 4;
        const int h = d >> 6;
        const int q = d & 63;
        float* Vb = R + V_BASE + b * VS_PER_B + h * ES_STRIDE + q;
        Vb[0] = v.x; Vb[1] = v.y; Vb[2] = v.z; Vb[3] = v.w;
    }
    __syncthreads();

    // Pass 2 register-tiled: 64 threads per b, each computes 4h x 4p outputs.
    // p = lp + 16*pp (conflict-free strided rows), h = lh + 4*hh (broadcast).
    {
        const int bsel = tt >> 6;          // 0..3
        const int u    = tt & 63;
        const int lp   = u & 15;
        const int lh   = u >> 4;
        const int b    = b0 + bsel;
        const float* ESb = ES + b * ES_PER_B;
        const float* Vb  = R + V_BASE + b * VS_PER_B;

        float oacc[4][4];                  // [hh][pp]
#pragma unroll
        for (int i = 0; i < 4; i++)
#pragma unroll
            for (int j = 0; j < 4; j++) oacc[i][j] = 0.f;

#pragma unroll
        for (int q = 0; q < 64; q += 4) {
            float4 e4[4], v4[4];
#pragma unroll
            for (int pp = 0; pp < 4; pp++)
                e4[pp] = *(const float4*)&ESb[(lp + 16 * pp) * ES_STRIDE + q];
#pragma unroll
            for (int hh = 0; hh < 4; hh++)
                v4[hh] = *(const float4*)&Vb[(lh + 4 * hh) * ES_STRIDE + q];
#pragma unroll
            for (int hh = 0; hh < 4; hh++)
#pragma unroll
                for (int pp = 0; pp < 4; pp++)
                    oacc[hh][pp] += e4[pp].x * v4[hh].x + e4[pp].y * v4[hh].y +
                                    e4[pp].z * v4[hh].z + e4[pp].w * v4[hh].w;
        }

        __half* ob = g_a16 + ((size_t)b * S_ + s) * D_;
#pragma unroll
        for (int hh = 0; hh < 4; hh++)
#pragma unroll
            for (int pp = 0; pp < 4; pp++)
                ob[(lh + 4 * hh) * 64 + lp + 16 * pp] = __float2half(oacc[hh][pp]);
    }
}

// ---------------------------------------------------------------------------
extern "C" void kernel_launch(void* const* d_in, const int* in_sizes, int n_in,
                              void* d_out, int out_size)
{
    const float* query = (const float*)d_in[0];
    const float* key   = (const float*)d_in[1];
    const float* value = (const float*)d_in[2];
    const float* Wq    = (const float*)d_in[3];
    const float* bq    = (const float*)d_in[4];
    const float* Wk    = (const float*)d_in[5];
    const float* bk    = (const float*)d_in[6];
    const float* Wv    = (const float*)d_in[7];
    const float* bv    = (const float*)d_in[8];
    const float* Wo    = (const float*)d_in[9];
    const float* bo    = (const float*)d_in[10];
    float* out = (float*)d_out;

    float *gQ, *gK, *gV;
    __half *q16, *k16, *v16, *a16, *wq16, *wk16, *wv16, *wo16;
    cudaGetSymbolAddress((void**)&gQ, g_Q);
    cudaGetSymbolAddress((void**)&gK, g_K);
    cudaGetSymbolAddress((void**)&gV, g_V);
    cudaGetSymbolAddress((void**)&q16, g_q16);
    cudaGetSymbolAddress((void**)&k16, g_k16);
    cudaGetSymbolAddress((void**)&v16, g_v16);
    cudaGetSymbolAddress((void**)&a16, g_a16);
    cudaGetSymbolAddress((void**)&wq16, g_wq16);
    cudaGetSymbolAddress((void**)&wk16, g_wk16);
    cudaGetSymbolAddress((void**)&wv16, g_wv16);
    cudaGetSymbolAddress((void**)&wo16, g_wo16);

    // Pre-convert inputs + weights to fp16
    const int nIn4 = (M_TOT * D_) / 4;    // 2M float4
    const int nW4  = (D_ * D_) / 4;       // 256K float4
    cvt16<<<(nIn4 + 255) / 256, 256>>>((const float4*)query, (uint2*)q16, nIn4);
    cvt16<<<(nIn4 + 255) / 256, 256>>>((const float4*)key,   (uint2*)k16, nIn4);
    cvt16<<<(nIn4 + 255) / 256, 256>>>((const float4*)value, (uint2*)v16, nIn4);
    cvt16<<<(nW4 + 255) / 256, 256>>>((const float4*)Wq, (uint2*)wq16, nW4);
    cvt16<<<(nW4 + 255) / 256, 256>>>((const float4*)Wk, (uint2*)wk16, nW4);
    cvt16<<<(nW4 + 255) / 256, 256>>>((const float4*)Wv, (uint2*)wv16, nW4);
    cvt16<<<(nW4 + 255) / 256, 256>>>((const float4*)Wo, (uint2*)wo16, nW4);

    cudaFuncSetAttribute(gemm_tc<0>,
                         cudaFuncAttributeMaxDynamicSharedMemorySize, GEMM_SMEM);
    cudaFuncSetAttribute(gemm_tc<1>,
                         cudaFuncAttributeMaxDynamicSharedMemorySize, GEMM_SMEM);

    dim3 grid(D_ / 128, M_TOT / 128);   // (8, 64)
    gemm_tc<0><<<grid, 512, GEMM_SMEM>>>(q16, wq16, bq, gQ);
    gemm_tc<0><<<grid, 512, GEMM_SMEM>>>(k16, wk16, bk, gK);
    gemm_tc<0><<<grid, 512, GEMM_SMEM>>>(v16, wv16, bv, gV);

    const size_t smem = SMEM_FLOATS * sizeof(float);   // 200 KB
    cudaFuncSetAttribute(attn_kernel,
                         cudaFuncAttributeMaxDynamicSharedMemorySize, (int)smem);
    attn_kernel<<<S_, 512, smem>>>();

    gemm_tc<1><<<grid, 512, GEMM_SMEM>>>(a16, wo16, bo, out);
}